// round 2
// baseline (speedup 1.0000x reference)
#include <cuda_runtime.h>
#include <cstdint>

#define N_EDGES 100000
#define N_ANGLES 400000
#define N_CRYST 512
#define EPS 1e-5f
#define INV_SQRT_2 0.70710678118654752440f

typedef unsigned long long ull;

// ---------- scratch (static device globals; no runtime allocation) ----------
__device__ float g_PQ[(size_t)N_EDGES * 512];   // P | Q
__device__ float g_h[(size_t)N_ANGLES * 256];
__device__ float g_sum[N_CRYST * 256];
__device__ float g_sumsq[N_CRYST * 256];
__device__ int   g_cnt[N_CRYST];
__device__ float g_ca[N_CRYST * 256];
__device__ float g_cb[N_CRYST * 256];
__device__ float g_s[(size_t)N_EDGES * 128];
__device__ int   g_ecnt[N_EDGES];

__device__ __forceinline__ ull pack2(float a, float b) {
    ull r; asm("mov.b64 %0, {%1, %2};" : "=l"(r) : "f"(a), "f"(b)); return r;
}
__device__ __forceinline__ void unpack2(ull v, float& a, float& b) {
    asm("mov.b64 {%0, %1}, %2;" : "=f"(a), "=f"(b) : "l"(v));
}
__device__ __forceinline__ ull fma2(ull a, ull b, ull c) {
    ull d; asm("fma.rn.f32x2 %0, %1, %2, %3;" : "=l"(d) : "l"(a), "l"(b), "l"(c)); return d;
}
__device__ __forceinline__ float silu_f(float x) { return x / (1.f + __expf(-x)); }

// ---------- K0: zero scratch ----------
__global__ void k_zero() {
    size_t i = (size_t)blockIdx.x * blockDim.x + threadIdx.x;
    size_t stride = (size_t)gridDim.x * blockDim.x;
    for (size_t t = i; t < (size_t)N_EDGES * 128; t += stride) g_s[t] = 0.f;
    for (size_t t = i; t < (size_t)N_EDGES; t += stride) g_ecnt[t] = 0;
    for (size_t t = i; t < (size_t)N_CRYST * 256; t += stride) { g_sum[t] = 0.f; g_sumsq[t] = 0.f; }
    for (size_t t = i; t < (size_t)N_CRYST; t += stride) g_cnt[t] = 0;
}

// ---------- shared GEMM body: 64x256 block tile, 8x8 per thread, FFMA2 ------
struct GemmSmem { float a[32][64]; float w[32][256]; };

__device__ __forceinline__ void gemm_tile_mm(GemmSmem& sm, int m0, int n0, ull acc2[8][4]) {
#pragma unroll
    for (int k = 0; k < 32; k++) {
        float4 A0 = *reinterpret_cast<float4*>(&sm.a[k][m0]);
        float4 A1 = *reinterpret_cast<float4*>(&sm.a[k][m0 + 4]);
        ull w2[4];
        w2[0] = *reinterpret_cast<ull*>(&sm.w[k][n0]);
        w2[1] = *reinterpret_cast<ull*>(&sm.w[k][n0 + 2]);
        w2[2] = *reinterpret_cast<ull*>(&sm.w[k][n0 + 4]);
        w2[3] = *reinterpret_cast<ull*>(&sm.w[k][n0 + 6]);
        float av[8] = {A0.x, A0.y, A0.z, A0.w, A1.x, A1.y, A1.z, A1.w};
#pragma unroll
        for (int i = 0; i < 8; i++) {
            ull a2 = pack2(av[i], av[i]);
#pragma unroll
            for (int j = 0; j < 4; j++) acc2[i][j] = fma2(a2, w2[j], acc2[i][j]);
        }
    }
}

// ---------- K1a: P/Q = nbr_fea @ W[:,64:192].T / W[:,192:320].T -------------
__global__ void k_gemm_pq(const float* __restrict__ nbr, const float* __restrict__ W) {
    __shared__ GemmSmem sm;
    int tid = threadIdx.x;
    int tx = tid & 31, ty = tid >> 5;
    int m0 = ty * 8, n0 = tx * 8;
    int m_base = blockIdx.x * 64;
    int koff = 64 + (int)blockIdx.y * 128;

    ull acc2[8][4];
#pragma unroll
    for (int i = 0; i < 8; i++)
#pragma unroll
        for (int j = 0; j < 4; j++) acc2[i][j] = 0ull;

    for (int kc = 0; kc < 4; kc++) {
        int k0 = kc * 32;
#pragma unroll
        for (int it = 0; it < 2; it++) {
            int lin = tid * 2 + it;
            int r = lin >> 3, q = lin & 7;
            int grow = m_base + r; if (grow >= N_EDGES) grow = N_EDGES - 1;
            float4 v = *reinterpret_cast<const float4*>(nbr + (size_t)grow * 128 + k0 + q * 4);
            sm.a[q * 4 + 0][r] = v.x; sm.a[q * 4 + 1][r] = v.y;
            sm.a[q * 4 + 2][r] = v.z; sm.a[q * 4 + 3][r] = v.w;
        }
#pragma unroll
        for (int it = 0; it < 8; it++) {
            int lin = it * 256 + tid;
            int n = lin >> 3, q = lin & 7;
            float4 v = *reinterpret_cast<const float4*>(W + (size_t)n * 320 + koff + k0 + q * 4);
            sm.w[q * 4 + 0][n] = v.x; sm.w[q * 4 + 1][n] = v.y;
            sm.w[q * 4 + 2][n] = v.z; sm.w[q * 4 + 3][n] = v.w;
        }
        __syncthreads();
        gemm_tile_mm(sm, m0, n0, acc2);
        __syncthreads();
    }
    int colbase = (int)blockIdx.y * 256 + n0;
#pragma unroll
    for (int i = 0; i < 8; i++) {
        int grow = m_base + m0 + i;
        if (grow < N_EDGES) {
            float o[8];
#pragma unroll
            for (int j = 0; j < 4; j++) unpack2(acc2[i][j], o[2 * j], o[2 * j + 1]);
            float4 v0 = {o[0], o[1], o[2], o[3]};
            float4 v1 = {o[4], o[5], o[6], o[7]};
            *reinterpret_cast<float4*>(&g_PQ[(size_t)grow * 512 + colbase]) = v0;
            *reinterpret_cast<float4*>(&g_PQ[(size_t)grow * 512 + colbase + 4]) = v1;
        }
    }
}

// ---------- K1b: h = angle_fea @ W[:,0:64].T + P[i0] + Q[i1] ----------------
__global__ void k_gemm_angle(const float* __restrict__ ang, const float* __restrict__ W,
                             const int* __restrict__ nidx) {
    __shared__ GemmSmem sm;
    int tid = threadIdx.x;
    int tx = tid & 31, ty = tid >> 5;
    int m0 = ty * 8, n0 = tx * 8;
    int m_base = blockIdx.x * 64;

    ull acc2[8][4];
#pragma unroll
    for (int i = 0; i < 8; i++)
#pragma unroll
        for (int j = 0; j < 4; j++) acc2[i][j] = 0ull;

    for (int kc = 0; kc < 2; kc++) {
        int k0 = kc * 32;
#pragma unroll
        for (int it = 0; it < 2; it++) {
            int lin = tid * 2 + it;
            int r = lin >> 3, q = lin & 7;
            float4 v = *reinterpret_cast<const float4*>(ang + (size_t)(m_base + r) * 64 + k0 + q * 4);
            sm.a[q * 4 + 0][r] = v.x; sm.a[q * 4 + 1][r] = v.y;
            sm.a[q * 4 + 2][r] = v.z; sm.a[q * 4 + 3][r] = v.w;
        }
#pragma unroll
        for (int it = 0; it < 8; it++) {
            int lin = it * 256 + tid;
            int n = lin >> 3, q = lin & 7;
            float4 v = *reinterpret_cast<const float4*>(W + (size_t)n * 320 + k0 + q * 4);
            sm.w[q * 4 + 0][n] = v.x; sm.w[q * 4 + 1][n] = v.y;
            sm.w[q * 4 + 2][n] = v.z; sm.w[q * 4 + 3][n] = v.w;
        }
        __syncthreads();
        gemm_tile_mm(sm, m0, n0, acc2);
        __syncthreads();
    }
#pragma unroll
    for (int i = 0; i < 8; i++) {
        int grow = m_base + m0 + i;
        int i0 = nidx[grow * 2 + 0];
        int i1 = nidx[grow * 2 + 1];
        float o[8];
#pragma unroll
        for (int j = 0; j < 4; j++) unpack2(acc2[i][j], o[2 * j], o[2 * j + 1]);
#pragma unroll
        for (int jj = 0; jj < 2; jj++) {
            float4 p = *reinterpret_cast<const float4*>(&g_PQ[(size_t)i0 * 512 + n0 + jj * 4]);
            float4 q = *reinterpret_cast<const float4*>(&g_PQ[(size_t)i1 * 512 + 256 + n0 + jj * 4]);
            float4 r;
            r.x = o[jj * 4 + 0] + p.x + q.x;
            r.y = o[jj * 4 + 1] + p.y + q.y;
            r.z = o[jj * 4 + 2] + p.z + q.z;
            r.w = o[jj * 4 + 3] + p.w + q.w;
            *reinterpret_cast<float4*>(&g_h[(size_t)grow * 256 + n0 + jj * 4]) = r;
        }
    }
}

// ---------- K2: per-crystal sum/sumsq/count (segments are sorted) -----------
__global__ void k_stats(const int* __restrict__ seg) {
    __shared__ int seg_sm[128];
    int tid = threadIdx.x;                   // 0..255 (column)
    int base = blockIdx.x * 128;
    if (tid < 128) seg_sm[tid] = seg[base + tid];
    __syncthreads();
    int cur = seg_sm[0];
    float s = 0.f, q = 0.f; int c = 0;
    for (int r = 0; r < 128; r++) {
        int sg = seg_sm[r];
        if (sg != cur) {
            atomicAdd(&g_sum[cur * 256 + tid], s);
            atomicAdd(&g_sumsq[cur * 256 + tid], q);
            if (tid == 0) atomicAdd(&g_cnt[cur], c);
            s = 0.f; q = 0.f; c = 0; cur = sg;
        }
        float v = g_h[(size_t)(base + r) * 256 + tid];
        s += v; q += v * v; c++;
    }
    atomicAdd(&g_sum[cur * 256 + tid], s);
    atomicAdd(&g_sumsq[cur * 256 + tid], q);
    if (tid == 0) atomicAdd(&g_cnt[cur], c);
}

// ---------- K3: crystal-norm affine coefficients ----------------------------
__global__ void k_finalize(const float* __restrict__ gamma, const float* __restrict__ beta) {
    int c = blockIdx.x, n = threadIdx.x;
    float cnt = fmaxf((float)g_cnt[c], 1.f);
    float mean = g_sum[c * 256 + n] / cnt;
    float var = fmaxf(g_sumsq[c * 256 + n] / cnt - mean * mean, 0.f);
    float a = gamma[n] * rsqrtf(var + EPS);
    g_ca[c * 256 + n] = a;
    g_cb[c * 256 + n] = beta[n] - mean * a;
}

// ---------- K4: per-angle msg + scatter into edge sums (1 warp/angle) -------
__global__ void k_msg(const int* __restrict__ seg, const int* __restrict__ nidx,
                      const float* __restrict__ Wm, const float* __restrict__ lng,
                      const float* __restrict__ lnb) {
    int lane = threadIdx.x & 31;
    int row = blockIdx.x * 8 + (threadIdx.x >> 5);
    const float4* hr = reinterpret_cast<const float4*>(&g_h[(size_t)row * 256]);
    float4 hc = hr[lane];
    float4 hf = hr[32 + lane];
    int sg = seg[row];
    const float4* ca = reinterpret_cast<const float4*>(&g_ca[(size_t)sg * 256]);
    const float4* cb = reinterpret_cast<const float4*>(&g_cb[(size_t)sg * 256]);
    float4 ac = ca[lane], af = ca[32 + lane];
    float4 bc = cb[lane], bf = cb[32 + lane];
    float4 core, filt;
    core.x = hc.x * ac.x + bc.x; core.y = hc.y * ac.y + bc.y;
    core.z = hc.z * ac.z + bc.z; core.w = hc.w * ac.w + bc.w;
    filt.x = hf.x * af.x + bf.x; filt.y = hf.y * af.y + bf.y;
    filt.z = hf.z * af.z + bf.z; filt.w = hf.w * af.w + bf.w;
    float s1 = core.x + core.y + core.z + core.w;
    float s2 = core.x * core.x + core.y * core.y + core.z * core.z + core.w * core.w;
#pragma unroll
    for (int off = 16; off >= 1; off >>= 1) {
        s1 += __shfl_xor_sync(0xffffffffu, s1, off);
        s2 += __shfl_xor_sync(0xffffffffu, s2, off);
    }
    float mean = s1 * (1.f / 128.f);
    float var = fmaxf(s2 * (1.f / 128.f) - mean * mean, 0.f);
    float rstd = rsqrtf(var + EPS);
    float4 g4 = reinterpret_cast<const float4*>(lng)[lane];
    float4 b4 = reinterpret_cast<const float4*>(lnb)[lane];
    float4 sl;
    sl.x = silu_f((core.x - mean) * rstd * g4.x + b4.x);
    sl.y = silu_f((core.y - mean) * rstd * g4.y + b4.y);
    sl.z = silu_f((core.z - mean) * rstd * g4.z + b4.z);
    sl.w = silu_f((core.w - mean) * rstd * g4.w + b4.w);
    float4 wm = reinterpret_cast<const float4*>(Wm)[lane];
    float gp = filt.x * wm.x + filt.y * wm.y + filt.z * wm.z + filt.w * wm.w;
#pragma unroll
    for (int off = 16; off >= 1; off >>= 1) gp += __shfl_xor_sync(0xffffffffu, gp, off);
    float gate = 1.f / (1.f + __expf(-gp));
    float4 msg = {gate * sl.x, gate * sl.y, gate * sl.z, gate * sl.w};
    int src = nidx[row * 2];
    float* dst = &g_s[(size_t)src * 128 + lane * 4];
    asm volatile("red.global.add.v4.f32 [%0], {%1,%2,%3,%4};"
                 :: "l"(dst), "f"(msg.x), "f"(msg.y), "f"(msg.z), "f"(msg.w) : "memory");
    if (lane == 0) atomicAdd(&g_ecnt[src], 1);
}

// ---------- K5: per-edge LN2 + two residual MLPs + output -------------------
__global__ void k_edge(const float* __restrict__ nbr,
                       const float* __restrict__ ln2g, const float* __restrict__ ln2b,
                       const float* __restrict__ W1a, const float* __restrict__ b1a,
                       const float* __restrict__ W2a, const float* __restrict__ b2a,
                       const float* __restrict__ W1b, const float* __restrict__ b1b,
                       const float* __restrict__ W2b, const float* __restrict__ b2b,
                       float* __restrict__ out) {
    extern __shared__ float sm[];
    float* W1aT = sm;             // [128][64]  (d*64+j)
    float* W2aS = sm + 8192;      // [64][128]  (j*128+d)
    float* W1bT = sm + 16384;
    float* W2bS = sm + 24576;
    float* b1as = sm + 32768;     // 64
    float* b2as = sm + 32832;     // 128
    float* b1bs = sm + 32960;     // 64
    float* b2bs = sm + 33024;     // 128
    float* g2s  = sm + 33152;     // 128
    float* bb2s = sm + 33280;     // 128
    float* x_sm = sm + 33408;     // [16][128]
    float* h1_sm = sm + 35456;    // [16][64]

    int tid = threadIdx.x;
    for (int i = tid; i < 8192; i += 256) {
        int j = i >> 7, d = i & 127;      // W1 is [64][128]
        W1aT[d * 64 + j] = W1a[i];
        W1bT[d * 64 + j] = W1b[i];
        int d2 = i >> 6, j2 = i & 63;     // W2 is [128][64]
        W2aS[j2 * 128 + d2] = W2a[i];
        W2bS[j2 * 128 + d2] = W2b[i];
    }
    if (tid < 64) { b1as[tid] = b1a[tid]; b1bs[tid] = b1b[tid]; }
    else if (tid >= 128 && tid < 256) {
        int t = tid - 128;
        b2as[t] = b2a[t]; b2bs[t] = b2b[t]; g2s[t] = ln2g[t]; bb2s[t] = ln2b[t];
    }
    __syncthreads();

    for (int grp = blockIdx.x; grp < N_EDGES / 16; grp += gridDim.x) {
        int e_base = grp * 16;
        { // Phase A: mean-msg + LN2 -> x_sm
            int eL = tid >> 4, l16 = tid & 15;
            int e = e_base + eL;
            float inv = 1.f / fmaxf((float)g_ecnt[e], 1.f);
            const float4* sp = reinterpret_cast<const float4*>(&g_s[(size_t)e * 128]);
            float4 v0 = sp[l16 * 2], v1 = sp[l16 * 2 + 1];
            float vals[8] = {v0.x * inv, v0.y * inv, v0.z * inv, v0.w * inv,
                             v1.x * inv, v1.y * inv, v1.z * inv, v1.w * inv};
            float s1 = 0.f, s2 = 0.f;
#pragma unroll
            for (int k = 0; k < 8; k++) { s1 += vals[k]; s2 += vals[k] * vals[k]; }
#pragma unroll
            for (int off = 8; off >= 1; off >>= 1) {
                s1 += __shfl_xor_sync(0xffffffffu, s1, off);
                s2 += __shfl_xor_sync(0xffffffffu, s2, off);
            }
            float mean = s1 * (1.f / 128.f);
            float var = fmaxf(s2 * (1.f / 128.f) - mean * mean, 0.f);
            float rstd = rsqrtf(var + EPS);
            int d0 = l16 * 8;
#pragma unroll
            for (int k = 0; k < 8; k++)
                x_sm[eL * 128 + d0 + k] = (vals[k] - mean) * rstd * g2s[d0 + k] + bb2s[d0 + k];
        }
        __syncthreads();
        { // MLP A hidden
            int j = tid & 63, g = tid >> 6;
            float a0 = b1as[j], a1 = a0, a2 = a0, a3 = a0;
            const float* xb = &x_sm[(g * 4) * 128];
#pragma unroll 8
            for (int d = 0; d < 128; d += 4) {
                float w0 = W1aT[d * 64 + j], w1 = W1aT[(d + 1) * 64 + j];
                float w2 = W1aT[(d + 2) * 64 + j], w3 = W1aT[(d + 3) * 64 + j];
                float4 x0 = *reinterpret_cast<const float4*>(&xb[0 * 128 + d]);
                float4 x1 = *reinterpret_cast<const float4*>(&xb[1 * 128 + d]);
                float4 x2 = *reinterpret_cast<const float4*>(&xb[2 * 128 + d]);
                float4 x3 = *reinterpret_cast<const float4*>(&xb[3 * 128 + d]);
                a0 += x0.x * w0 + x0.y * w1 + x0.z * w2 + x0.w * w3;
                a1 += x1.x * w0 + x1.y * w1 + x1.z * w2 + x1.w * w3;
                a2 += x2.x * w0 + x2.y * w1 + x2.z * w2 + x2.w * w3;
                a3 += x3.x * w0 + x3.y * w1 + x3.z * w2 + x3.w * w3;
            }
            h1_sm[(g * 4 + 0) * 64 + j] = silu_f(a0);
            h1_sm[(g * 4 + 1) * 64 + j] = silu_f(a1);
            h1_sm[(g * 4 + 2) * 64 + j] = silu_f(a2);
            h1_sm[(g * 4 + 3) * 64 + j] = silu_f(a3);
        }
        __syncthreads();
        { // MLP A out + residual
            int d = tid & 127, gg = tid >> 7;
            float acc[8];
#pragma unroll
            for (int e = 0; e < 8; e++) acc[e] = b2as[d];
#pragma unroll 8
            for (int j = 0; j < 64; j += 4) {
                float w0 = W2aS[j * 128 + d], w1 = W2aS[(j + 1) * 128 + d];
                float w2 = W2aS[(j + 2) * 128 + d], w3 = W2aS[(j + 3) * 128 + d];
#pragma unroll
                for (int e = 0; e < 8; e++) {
                    float4 h = *reinterpret_cast<const float4*>(&h1_sm[(gg * 8 + e) * 64 + j]);
                    acc[e] += h.x * w0 + h.y * w1 + h.z * w2 + h.w * w3;
                }
            }
#pragma unroll
            for (int e = 0; e < 8; e++) x_sm[(gg * 8 + e) * 128 + d] += acc[e];
        }
        __syncthreads();
        { // MLP B hidden
            int j = tid & 63, g = tid >> 6;
            float a0 = b1bs[j], a1 = a0, a2 = a0, a3 = a0;
            const float* xb = &x_sm[(g * 4) * 128];
#pragma unroll 8
            for (int d = 0; d < 128; d += 4) {
                float w0 = W1bT[d * 64 + j], w1 = W1bT[(d + 1) * 64 + j];
                float w2 = W1bT[(d + 2) * 64 + j], w3 = W1bT[(d + 3) * 64 + j];
                float4 x0 = *reinterpret_cast<const float4*>(&xb[0 * 128 + d]);
                float4 x1 = *reinterpret_cast<const float4*>(&xb[1 * 128 + d]);
                float4 x2 = *reinterpret_cast<const float4*>(&xb[2 * 128 + d]);
                float4 x3 = *reinterpret_cast<const float4*>(&xb[3 * 128 + d]);
                a0 += x0.x * w0 + x0.y * w1 + x0.z * w2 + x0.w * w3;
                a1 += x1.x * w0 + x1.y * w1 + x1.z * w2 + x1.w * w3;
                a2 += x2.x * w0 + x2.y * w1 + x2.z * w2 + x2.w * w3;
                a3 += x3.x * w0 + x3.y * w1 + x3.z * w2 + x3.w * w3;
            }
            h1_sm[(g * 4 + 0) * 64 + j] = silu_f(a0);
            h1_sm[(g * 4 + 1) * 64 + j] = silu_f(a1);
            h1_sm[(g * 4 + 2) * 64 + j] = silu_f(a2);
            h1_sm[(g * 4 + 3) * 64 + j] = silu_f(a3);
        }
        __syncthreads();
        { // MLP B out + residual + final output
            int d = tid & 127, gg = tid >> 7;
            float acc[8];
#pragma unroll
            for (int e = 0; e < 8; e++) acc[e] = b2bs[d];
#pragma unroll 8
            for (int j = 0; j < 64; j += 4) {
                float w0 = W2bS[j * 128 + d], w1 = W2bS[(j + 1) * 128 + d];
                float w2 = W2bS[(j + 2) * 128 + d], w3 = W2bS[(j + 3) * 128 + d];
#pragma unroll
                for (int e = 0; e < 8; e++) {
                    float4 h = *reinterpret_cast<const float4*>(&h1_sm[(gg * 8 + e) * 64 + j]);
                    acc[e] += h.x * w0 + h.y * w1 + h.z * w2 + h.w * w3;
                }
            }
#pragma unroll
            for (int e = 0; e < 8; e++) {
                int eg = e_base + gg * 8 + e;
                float xf = x_sm[(gg * 8 + e) * 128 + d] + acc[e];
                out[(size_t)eg * 128 + d] = INV_SQRT_2 * (nbr[(size_t)eg * 128 + d] + xf);
            }
        }
        __syncthreads();
    }
}

// ---------- launch ----------------------------------------------------------
extern "C" void kernel_launch(void* const* d_in, const int* in_sizes, int n_in,
                              void* d_out, int out_size) {
    const float* nbr_fea   = (const float*)d_in[0];
    const float* angle_fea = (const float*)d_in[1];
    const int*   nidx      = (const int*)d_in[2];
    // d_in[3] = crystal_edge_idx (unused by the reference)
    const int*   cai       = (const int*)d_in[4];
    const float* W_full    = (const float*)d_in[5];
    const float* W_mask    = (const float*)d_in[6];
    const float* cn_gamma  = (const float*)d_in[7];
    const float* cn_beta   = (const float*)d_in[8];
    const float* ln_core_g = (const float*)d_in[9];
    const float* ln_core_b = (const float*)d_in[10];
    const float* ln2_g     = (const float*)d_in[11];
    const float* ln2_b     = (const float*)d_in[12];
    const float* res_W1a   = (const float*)d_in[13];
    const float* res_b1a   = (const float*)d_in[14];
    const float* res_W2a   = (const float*)d_in[15];
    const float* res_b2a   = (const float*)d_in[16];
    const float* res_W1b   = (const float*)d_in[17];
    const float* res_b1b   = (const float*)d_in[18];
    const float* res_W2b   = (const float*)d_in[19];
    const float* res_b2b   = (const float*)d_in[20];
    float* out = (float*)d_out;

    static bool attr_set = false;
    if (!attr_set) {
        cudaFuncSetAttribute(k_edge, cudaFuncAttributeMaxDynamicSharedMemorySize, 146 * 1024);
        attr_set = true;
    }

    k_zero<<<1024, 256>>>();
    k_gemm_pq<<<dim3((N_EDGES + 63) / 64, 2), 256>>>(nbr_fea, W_full);
    k_gemm_angle<<<N_ANGLES / 64, 256>>>(angle_fea, W_full, nidx);
    k_stats<<<N_ANGLES / 128, 256>>>(cai);
    k_finalize<<<N_CRYST, 256>>>(cn_gamma, cn_beta);
    k_msg<<<N_ANGLES / 8, 256>>>(cai, nidx, W_mask, ln_core_g, ln_core_b);
    k_edge<<<160, 256, 36480 * sizeof(float)>>>(nbr_fea, ln2_g, ln2_b,
                                                res_W1a, res_b1a, res_W2a, res_b2a,
                                                res_W1b, res_b1b, res_W2b, res_b2b, out);
}

// round 3
// speedup vs baseline: 1.2898x; 1.2898x over previous
#include <cuda_runtime.h>
#include <cstdint>

#define N_EDGES 100000
#define N_ANGLES 400000
#define N_CRYST 512
#define EPS 1e-5f
#define INV_SQRT_2 0.70710678118654752440f

typedef unsigned long long ull;

// ---------- scratch (static device globals; no runtime allocation) ----------
__device__ float g_PQ[(size_t)N_EDGES * 512];   // P | Q
__device__ float g_h[(size_t)N_ANGLES * 256];
__device__ float g_sum[N_CRYST * 256];
__device__ float g_sumsq[N_CRYST * 256];
__device__ int   g_cnt[N_CRYST];
__device__ float g_ca[N_CRYST * 256];
__device__ float g_cb[N_CRYST * 256];
__device__ float g_s[(size_t)N_EDGES * 128];
__device__ int   g_ecnt[N_EDGES];

__device__ __forceinline__ ull pack2(float a, float b) {
    ull r; asm("mov.b64 %0, {%1, %2};" : "=l"(r) : "f"(a), "f"(b)); return r;
}
__device__ __forceinline__ void unpack2(ull v, float& a, float& b) {
    asm("mov.b64 {%0, %1}, %2;" : "=f"(a), "=f"(b) : "l"(v));
}
__device__ __forceinline__ ull fma2(ull a, ull b, ull c) {
    ull d; asm("fma.rn.f32x2 %0, %1, %2, %3;" : "=l"(d) : "l"(a), "l"(b), "l"(c)); return d;
}
__device__ __forceinline__ float silu_f(float x) { return x / (1.f + __expf(-x)); }

// ---------- K0: zero scratch ----------
__global__ void k_zero() {
    size_t i = (size_t)blockIdx.x * blockDim.x + threadIdx.x;
    size_t stride = (size_t)gridDim.x * blockDim.x;
    for (size_t t = i; t < (size_t)N_EDGES * 128; t += stride) g_s[t] = 0.f;
    for (size_t t = i; t < (size_t)N_EDGES; t += stride) g_ecnt[t] = 0;
    for (size_t t = i; t < (size_t)N_CRYST * 256; t += stride) { g_sum[t] = 0.f; g_sumsq[t] = 0.f; }
    for (size_t t = i; t < (size_t)N_CRYST; t += stride) g_cnt[t] = 0;
}

// ---------- shared GEMM body: 64x256 block tile, 8x8 per thread, FFMA2 ------
struct GemmSmem { float a[32][64]; float w[32][256]; };

__device__ __forceinline__ void gemm_tile_mm(GemmSmem& sm, int m0, int n0, ull acc2[8][4]) {
#pragma unroll
    for (int k = 0; k < 32; k++) {
        float4 A0 = *reinterpret_cast<float4*>(&sm.a[k][m0]);
        float4 A1 = *reinterpret_cast<float4*>(&sm.a[k][m0 + 4]);
        ull w2[4];
        w2[0] = *reinterpret_cast<ull*>(&sm.w[k][n0]);
        w2[1] = *reinterpret_cast<ull*>(&sm.w[k][n0 + 2]);
        w2[2] = *reinterpret_cast<ull*>(&sm.w[k][n0 + 4]);
        w2[3] = *reinterpret_cast<ull*>(&sm.w[k][n0 + 6]);
        float av[8] = {A0.x, A0.y, A0.z, A0.w, A1.x, A1.y, A1.z, A1.w};
#pragma unroll
        for (int i = 0; i < 8; i++) {
            ull a2 = pack2(av[i], av[i]);
#pragma unroll
            for (int j = 0; j < 4; j++) acc2[i][j] = fma2(a2, w2[j], acc2[i][j]);
        }
    }
}

// ---------- K1a: P/Q = nbr_fea @ W[:,64:192].T / W[:,192:320].T -------------
__global__ __launch_bounds__(256) void k_gemm_pq(const float* __restrict__ nbr,
                                                 const float* __restrict__ W) {
    __shared__ GemmSmem sm;
    int tid = threadIdx.x;
    int tx = tid & 31, ty = tid >> 5;
    int m0 = ty * 8, n0 = tx * 8;
    int m_base = blockIdx.x * 64;
    int koff = 64 + (int)blockIdx.y * 128;

    ull acc2[8][4];
#pragma unroll
    for (int i = 0; i < 8; i++)
#pragma unroll
        for (int j = 0; j < 4; j++) acc2[i][j] = 0ull;

    for (int kc = 0; kc < 4; kc++) {
        int k0 = kc * 32;
#pragma unroll
        for (int it = 0; it < 2; it++) {
            int lin = tid * 2 + it;
            int r = lin >> 3, q = lin & 7;
            int grow = m_base + r; if (grow >= N_EDGES) grow = N_EDGES - 1;
            float4 v = *reinterpret_cast<const float4*>(nbr + (size_t)grow * 128 + k0 + q * 4);
            sm.a[q * 4 + 0][r] = v.x; sm.a[q * 4 + 1][r] = v.y;
            sm.a[q * 4 + 2][r] = v.z; sm.a[q * 4 + 3][r] = v.w;
        }
#pragma unroll
        for (int it = 0; it < 8; it++) {
            int lin = it * 256 + tid;
            int n = lin >> 3, q = lin & 7;
            float4 v = *reinterpret_cast<const float4*>(W + (size_t)n * 320 + koff + k0 + q * 4);
            sm.w[q * 4 + 0][n] = v.x; sm.w[q * 4 + 1][n] = v.y;
            sm.w[q * 4 + 2][n] = v.z; sm.w[q * 4 + 3][n] = v.w;
        }
        __syncthreads();
        gemm_tile_mm(sm, m0, n0, acc2);
        __syncthreads();
    }
    int colbase = (int)blockIdx.y * 256 + n0;
#pragma unroll
    for (int i = 0; i < 8; i++) {
        int grow = m_base + m0 + i;
        if (grow < N_EDGES) {
            float o[8];
#pragma unroll
            for (int j = 0; j < 4; j++) unpack2(acc2[i][j], o[2 * j], o[2 * j + 1]);
            float4 v0 = {o[0], o[1], o[2], o[3]};
            float4 v1 = {o[4], o[5], o[6], o[7]};
            *reinterpret_cast<float4*>(&g_PQ[(size_t)grow * 512 + colbase]) = v0;
            *reinterpret_cast<float4*>(&g_PQ[(size_t)grow * 512 + colbase + 4]) = v1;
        }
    }
}

// ---------- K1b: h = angle@Wa.T + P[i0] + Q[i1], FUSED crystal stats --------
// Angles are sorted by crystal (~781 rows/crystal), so a 64-row block spans
// at most 2 crystals in practice. Accumulate sum/sumsq into 2 smem slots and
// flush once per block; safe fallback to direct global atomics otherwise.
__global__ __launch_bounds__(256) void k_gemm_angle(const float* __restrict__ ang,
                                                    const float* __restrict__ W,
                                                    const int* __restrict__ nidx,
                                                    const int* __restrict__ seg) {
    __shared__ GemmSmem sm;
    __shared__ float sum_sm[2][256];
    __shared__ float sq_sm[2][256];
    __shared__ int cnt_sm[2];
    __shared__ int seg_sm[64];

    int tid = threadIdx.x;
    int tx = tid & 31, ty = tid >> 5;
    int m0 = ty * 8, n0 = tx * 8;
    int m_base = blockIdx.x * 64;

    // init stats smem + load seg
    sum_sm[0][tid] = 0.f; sum_sm[1][tid] = 0.f;
    sq_sm[0][tid] = 0.f;  sq_sm[1][tid] = 0.f;
    if (tid < 2) cnt_sm[tid] = 0;
    if (tid < 64) seg_sm[tid] = seg[m_base + tid];

    ull acc2[8][4];
#pragma unroll
    for (int i = 0; i < 8; i++)
#pragma unroll
        for (int j = 0; j < 4; j++) acc2[i][j] = 0ull;

    for (int kc = 0; kc < 2; kc++) {
        int k0 = kc * 32;
#pragma unroll
        for (int it = 0; it < 2; it++) {
            int lin = tid * 2 + it;
            int r = lin >> 3, q = lin & 7;
            float4 v = *reinterpret_cast<const float4*>(ang + (size_t)(m_base + r) * 64 + k0 + q * 4);
            sm.a[q * 4 + 0][r] = v.x; sm.a[q * 4 + 1][r] = v.y;
            sm.a[q * 4 + 2][r] = v.z; sm.a[q * 4 + 3][r] = v.w;
        }
#pragma unroll
        for (int it = 0; it < 8; it++) {
            int lin = it * 256 + tid;
            int n = lin >> 3, q = lin & 7;
            float4 v = *reinterpret_cast<const float4*>(W + (size_t)n * 320 + k0 + q * 4);
            sm.w[q * 4 + 0][n] = v.x; sm.w[q * 4 + 1][n] = v.y;
            sm.w[q * 4 + 2][n] = v.z; sm.w[q * 4 + 3][n] = v.w;
        }
        __syncthreads();
        gemm_tile_mm(sm, m0, n0, acc2);
        __syncthreads();
    }

    int seg_base = seg_sm[0];
    // counts: one thread per row
    if (tid < 64) {
        int slot = seg_sm[tid] - seg_base;
        if (slot == 0 || slot == 1) atomicAdd(&cnt_sm[slot], 1);
        else atomicAdd(&g_cnt[seg_sm[tid]], 1);
    }

    float accS[8], accQ[8];
#pragma unroll
    for (int j = 0; j < 8; j++) { accS[j] = 0.f; accQ[j] = 0.f; }
    int cur_slot = -1;

#pragma unroll
    for (int i = 0; i < 8; i++) {
        int grow = m_base + m0 + i;
        int i0 = nidx[grow * 2 + 0];
        int i1 = nidx[grow * 2 + 1];
        float o[8];
#pragma unroll
        for (int j = 0; j < 4; j++) unpack2(acc2[i][j], o[2 * j], o[2 * j + 1]);
        float vs[8];
#pragma unroll
        for (int jj = 0; jj < 2; jj++) {
            float4 p = *reinterpret_cast<const float4*>(&g_PQ[(size_t)i0 * 512 + n0 + jj * 4]);
            float4 q = *reinterpret_cast<const float4*>(&g_PQ[(size_t)i1 * 512 + 256 + n0 + jj * 4]);
            float4 r;
            r.x = o[jj * 4 + 0] + p.x + q.x;
            r.y = o[jj * 4 + 1] + p.y + q.y;
            r.z = o[jj * 4 + 2] + p.z + q.z;
            r.w = o[jj * 4 + 3] + p.w + q.w;
            *reinterpret_cast<float4*>(&g_h[(size_t)grow * 256 + n0 + jj * 4]) = r;
            vs[jj * 4 + 0] = r.x; vs[jj * 4 + 1] = r.y;
            vs[jj * 4 + 2] = r.z; vs[jj * 4 + 3] = r.w;
        }
        int sg = seg_sm[m0 + i];
        int slot = sg - seg_base;
        if (slot == 0 || slot == 1) {
            if (slot != cur_slot) {
                if (cur_slot >= 0) {
#pragma unroll
                    for (int j = 0; j < 8; j++) {
                        atomicAdd(&sum_sm[cur_slot][n0 + j], accS[j]);
                        atomicAdd(&sq_sm[cur_slot][n0 + j], accQ[j]);
                        accS[j] = 0.f; accQ[j] = 0.f;
                    }
                }
                cur_slot = slot;
            }
#pragma unroll
            for (int j = 0; j < 8; j++) { accS[j] += vs[j]; accQ[j] += vs[j] * vs[j]; }
        } else { // pathological fallback (shouldn't happen with sorted segs)
#pragma unroll
            for (int j = 0; j < 8; j++) {
                atomicAdd(&g_sum[sg * 256 + n0 + j], vs[j]);
                atomicAdd(&g_sumsq[sg * 256 + n0 + j], vs[j] * vs[j]);
            }
        }
    }
    if (cur_slot >= 0) {
#pragma unroll
        for (int j = 0; j < 8; j++) {
            atomicAdd(&sum_sm[cur_slot][n0 + j], accS[j]);
            atomicAdd(&sq_sm[cur_slot][n0 + j], accQ[j]);
        }
    }
    __syncthreads();
    // block-level flush: 2 slots x 256 cols
#pragma unroll
    for (int slot = 0; slot < 2; slot++) {
        int sg = seg_base + slot;
        if (cnt_sm[slot] > 0 && sg < N_CRYST) {
            atomicAdd(&g_sum[sg * 256 + tid], sum_sm[slot][tid]);
            atomicAdd(&g_sumsq[sg * 256 + tid], sq_sm[slot][tid]);
            if (tid == 0) atomicAdd(&g_cnt[sg], cnt_sm[slot]);
        }
    }
}

// ---------- K3: crystal-norm affine coefficients ----------------------------
__global__ void k_finalize(const float* __restrict__ gamma, const float* __restrict__ beta) {
    int c = blockIdx.x, n = threadIdx.x;
    float cnt = fmaxf((float)g_cnt[c], 1.f);
    float mean = g_sum[c * 256 + n] / cnt;
    float var = fmaxf(g_sumsq[c * 256 + n] / cnt - mean * mean, 0.f);
    float a = gamma[n] * rsqrtf(var + EPS);
    g_ca[c * 256 + n] = a;
    g_cb[c * 256 + n] = beta[n] - mean * a;
}

// ---------- K4: per-angle msg + scatter into edge sums (1 warp/angle) -------
__global__ __launch_bounds__(256) void k_msg(const int* __restrict__ seg,
                                             const int* __restrict__ nidx,
                                             const float* __restrict__ Wm,
                                             const float* __restrict__ lng,
                                             const float* __restrict__ lnb) {
    int lane = threadIdx.x & 31;
    int row = blockIdx.x * 8 + (threadIdx.x >> 5);
    const float4* hr = reinterpret_cast<const float4*>(&g_h[(size_t)row * 256]);
    float4 hc = hr[lane];
    float4 hf = hr[32 + lane];
    int sg = seg[row];
    const float4* ca = reinterpret_cast<const float4*>(&g_ca[(size_t)sg * 256]);
    const float4* cb = reinterpret_cast<const float4*>(&g_cb[(size_t)sg * 256]);
    float4 ac = ca[lane], af = ca[32 + lane];
    float4 bc = cb[lane], bf = cb[32 + lane];
    float4 core, filt;
    core.x = hc.x * ac.x + bc.x; core.y = hc.y * ac.y + bc.y;
    core.z = hc.z * ac.z + bc.z; core.w = hc.w * ac.w + bc.w;
    filt.x = hf.x * af.x + bf.x; filt.y = hf.y * af.y + bf.y;
    filt.z = hf.z * af.z + bf.z; filt.w = hf.w * af.w + bf.w;
    float s1 = core.x + core.y + core.z + core.w;
    float s2 = core.x * core.x + core.y * core.y + core.z * core.z + core.w * core.w;
#pragma unroll
    for (int off = 16; off >= 1; off >>= 1) {
        s1 += __shfl_xor_sync(0xffffffffu, s1, off);
        s2 += __shfl_xor_sync(0xffffffffu, s2, off);
    }
    float mean = s1 * (1.f / 128.f);
    float var = fmaxf(s2 * (1.f / 128.f) - mean * mean, 0.f);
    float rstd = rsqrtf(var + EPS);
    float4 g4 = reinterpret_cast<const float4*>(lng)[lane];
    float4 b4 = reinterpret_cast<const float4*>(lnb)[lane];
    float4 sl;
    sl.x = silu_f((core.x - mean) * rstd * g4.x + b4.x);
    sl.y = silu_f((core.y - mean) * rstd * g4.y + b4.y);
    sl.z = silu_f((core.z - mean) * rstd * g4.z + b4.z);
    sl.w = silu_f((core.w - mean) * rstd * g4.w + b4.w);
    float4 wm = reinterpret_cast<const float4*>(Wm)[lane];
    float gp = filt.x * wm.x + filt.y * wm.y + filt.z * wm.z + filt.w * wm.w;
#pragma unroll
    for (int off = 16; off >= 1; off >>= 1) gp += __shfl_xor_sync(0xffffffffu, gp, off);
    float gate = 1.f / (1.f + __expf(-gp));
    float4 msg = {gate * sl.x, gate * sl.y, gate * sl.z, gate * sl.w};
    int src = nidx[row * 2];
    float* dst = &g_s[(size_t)src * 128 + lane * 4];
    asm volatile("red.global.add.v4.f32 [%0], {%1,%2,%3,%4};"
                 :: "l"(dst), "f"(msg.x), "f"(msg.y), "f"(msg.z), "f"(msg.w) : "memory");
    if (lane == 0) atomicAdd(&g_ecnt[src], 1);
}

// ---------- K5: per-edge LN2 + two residual MLPs + output -------------------
__global__ void k_edge(const float* __restrict__ nbr,
                       const float* __restrict__ ln2g, const float* __restrict__ ln2b,
                       const float* __restrict__ W1a, const float* __restrict__ b1a,
                       const float* __restrict__ W2a, const float* __restrict__ b2a,
                       const float* __restrict__ W1b, const float* __restrict__ b1b,
                       const float* __restrict__ W2b, const float* __restrict__ b2b,
                       float* __restrict__ out) {
    extern __shared__ float sm[];
    float* W1aT = sm;             // [128][64]  (d*64+j)
    float* W2aS = sm + 8192;      // [64][128]  (j*128+d)
    float* W1bT = sm + 16384;
    float* W2bS = sm + 24576;
    float* b1as = sm + 32768;     // 64
    float* b2as = sm + 32832;     // 128
    float* b1bs = sm + 32960;     // 64
    float* b2bs = sm + 33024;     // 128
    float* g2s  = sm + 33152;     // 128
    float* bb2s = sm + 33280;     // 128
    float* x_sm = sm + 33408;     // [16][128]
    float* h1_sm = sm + 35456;    // [16][64]

    int tid = threadIdx.x;
    for (int i = tid; i < 8192; i += 256) {
        int j = i >> 7, d = i & 127;      // W1 is [64][128]
        W1aT[d * 64 + j] = W1a[i];
        W1bT[d * 64 + j] = W1b[i];
        int d2 = i >> 6, j2 = i & 63;     // W2 is [128][64]
        W2aS[j2 * 128 + d2] = W2a[i];
        W2bS[j2 * 128 + d2] = W2b[i];
    }
    if (tid < 64) { b1as[tid] = b1a[tid]; b1bs[tid] = b1b[tid]; }
    else if (tid >= 128 && tid < 256) {
        int t = tid - 128;
        b2as[t] = b2a[t]; b2bs[t] = b2b[t]; g2s[t] = ln2g[t]; bb2s[t] = ln2b[t];
    }
    __syncthreads();

    for (int grp = blockIdx.x; grp < N_EDGES / 16; grp += gridDim.x) {
        int e_base = grp * 16;
        { // Phase A: mean-msg + LN2 -> x_sm
            int eL = tid >> 4, l16 = tid & 15;
            int e = e_base + eL;
            float inv = 1.f / fmaxf((float)g_ecnt[e], 1.f);
            const float4* sp = reinterpret_cast<const float4*>(&g_s[(size_t)e * 128]);
            float4 v0 = sp[l16 * 2], v1 = sp[l16 * 2 + 1];
            float vals[8] = {v0.x * inv, v0.y * inv, v0.z * inv, v0.w * inv,
                             v1.x * inv, v1.y * inv, v1.z * inv, v1.w * inv};
            float s1 = 0.f, s2 = 0.f;
#pragma unroll
            for (int k = 0; k < 8; k++) { s1 += vals[k]; s2 += vals[k] * vals[k]; }
#pragma unroll
            for (int off = 8; off >= 1; off >>= 1) {
                s1 += __shfl_xor_sync(0xffffffffu, s1, off);
                s2 += __shfl_xor_sync(0xffffffffu, s2, off);
            }
            float mean = s1 * (1.f / 128.f);
            float var = fmaxf(s2 * (1.f / 128.f) - mean * mean, 0.f);
            float rstd = rsqrtf(var + EPS);
            int d0 = l16 * 8;
#pragma unroll
            for (int k = 0; k < 8; k++)
                x_sm[eL * 128 + d0 + k] = (vals[k] - mean) * rstd * g2s[d0 + k] + bb2s[d0 + k];
        }
        __syncthreads();
        { // MLP A hidden
            int j = tid & 63, g = tid >> 6;
            float a0 = b1as[j], a1 = a0, a2 = a0, a3 = a0;
            const float* xb = &x_sm[(g * 4) * 128];
#pragma unroll 8
            for (int d = 0; d < 128; d += 4) {
                float w0 = W1aT[d * 64 + j], w1 = W1aT[(d + 1) * 64 + j];
                float w2 = W1aT[(d + 2) * 64 + j], w3 = W1aT[(d + 3) * 64 + j];
                float4 x0 = *reinterpret_cast<const float4*>(&xb[0 * 128 + d]);
                float4 x1 = *reinterpret_cast<const float4*>(&xb[1 * 128 + d]);
                float4 x2 = *reinterpret_cast<const float4*>(&xb[2 * 128 + d]);
                float4 x3 = *reinterpret_cast<const float4*>(&xb[3 * 128 + d]);
                a0 += x0.x * w0 + x0.y * w1 + x0.z * w2 + x0.w * w3;
                a1 += x1.x * w0 + x1.y * w1 + x1.z * w2 + x1.w * w3;
                a2 += x2.x * w0 + x2.y * w1 + x2.z * w2 + x2.w * w3;
                a3 += x3.x * w0 + x3.y * w1 + x3.z * w2 + x3.w * w3;
            }
            h1_sm[(g * 4 + 0) * 64 + j] = silu_f(a0);
            h1_sm[(g * 4 + 1) * 64 + j] = silu_f(a1);
            h1_sm[(g * 4 + 2) * 64 + j] = silu_f(a2);
            h1_sm[(g * 4 + 3) * 64 + j] = silu_f(a3);
        }
        __syncthreads();
        { // MLP A out + residual
            int d = tid & 127, gg = tid >> 7;
            float acc[8];
#pragma unroll
            for (int e = 0; e < 8; e++) acc[e] = b2as[d];
#pragma unroll 8
            for (int j = 0; j < 64; j += 4) {
                float w0 = W2aS[j * 128 + d], w1 = W2aS[(j + 1) * 128 + d];
                float w2 = W2aS[(j + 2) * 128 + d], w3 = W2aS[(j + 3) * 128 + d];
#pragma unroll
                for (int e = 0; e < 8; e++) {
                    float4 h = *reinterpret_cast<const float4*>(&h1_sm[(gg * 8 + e) * 64 + j]);
                    acc[e] += h.x * w0 + h.y * w1 + h.z * w2 + h.w * w3;
                }
            }
#pragma unroll
            for (int e = 0; e < 8; e++) x_sm[(gg * 8 + e) * 128 + d] += acc[e];
        }
        __syncthreads();
        { // MLP B hidden
            int j = tid & 63, g = tid >> 6;
            float a0 = b1bs[j], a1 = a0, a2 = a0, a3 = a0;
            const float* xb = &x_sm[(g * 4) * 128];
#pragma unroll 8
            for (int d = 0; d < 128; d += 4) {
                float w0 = W1bT[d * 64 + j], w1 = W1bT[(d + 1) * 64 + j];
                float w2 = W1bT[(d + 2) * 64 + j], w3 = W1bT[(d + 3) * 64 + j];
                float4 x0 = *reinterpret_cast<const float4*>(&xb[0 * 128 + d]);
                float4 x1 = *reinterpret_cast<const float4*>(&xb[1 * 128 + d]);
                float4 x2 = *reinterpret_cast<const float4*>(&xb[2 * 128 + d]);
                float4 x3 = *reinterpret_cast<const float4*>(&xb[3 * 128 + d]);
                a0 += x0.x * w0 + x0.y * w1 + x0.z * w2 + x0.w * w3;
                a1 += x1.x * w0 + x1.y * w1 + x1.z * w2 + x1.w * w3;
                a2 += x2.x * w0 + x2.y * w1 + x2.z * w2 + x2.w * w3;
                a3 += x3.x * w0 + x3.y * w1 + x3.z * w2 + x3.w * w3;
            }
            h1_sm[(g * 4 + 0) * 64 + j] = silu_f(a0);
            h1_sm[(g * 4 + 1) * 64 + j] = silu_f(a1);
            h1_sm[(g * 4 + 2) * 64 + j] = silu_f(a2);
            h1_sm[(g * 4 + 3) * 64 + j] = silu_f(a3);
        }
        __syncthreads();
        { // MLP B out + residual + final output
            int d = tid & 127, gg = tid >> 7;
            float acc[8];
#pragma unroll
            for (int e = 0; e < 8; e++) acc[e] = b2bs[d];
#pragma unroll 8
            for (int j = 0; j < 64; j += 4) {
                float w0 = W2bS[j * 128 + d], w1 = W2bS[(j + 1) * 128 + d];
                float w2 = W2bS[(j + 2) * 128 + d], w3 = W2bS[(j + 3) * 128 + d];
#pragma unroll
                for (int e = 0; e < 8; e++) {
                    float4 h = *reinterpret_cast<const float4*>(&h1_sm[(gg * 8 + e) * 64 + j]);
                    acc[e] += h.x * w0 + h.y * w1 + h.z * w2 + h.w * w3;
                }
            }
#pragma unroll
            for (int e = 0; e < 8; e++) {
                int eg = e_base + gg * 8 + e;
                float xf = x_sm[(gg * 8 + e) * 128 + d] + acc[e];
                out[(size_t)eg * 128 + d] = INV_SQRT_2 * (nbr[(size_t)eg * 128 + d] + xf);
            }
        }
        __syncthreads();
    }
}

// ---------- launch ----------------------------------------------------------
extern "C" void kernel_launch(void* const* d_in, const int* in_sizes, int n_in,
                              void* d_out, int out_size) {
    const float* nbr_fea   = (const float*)d_in[0];
    const float* angle_fea = (const float*)d_in[1];
    const int*   nidx      = (const int*)d_in[2];
    const int*   cai       = (const int*)d_in[4];
    const float* W_full    = (const float*)d_in[5];
    const float* W_mask    = (const float*)d_in[6];
    const float* cn_gamma  = (const float*)d_in[7];
    const float* cn_beta   = (const float*)d_in[8];
    const float* ln_core_g = (const float*)d_in[9];
    const float* ln_core_b = (const float*)d_in[10];
    const float* ln2_g     = (const float*)d_in[11];
    const float* ln2_b     = (const float*)d_in[12];
    const float* res_W1a   = (const float*)d_in[13];
    const float* res_b1a   = (const float*)d_in[14];
    const float* res_W2a   = (const float*)d_in[15];
    const float* res_b2a   = (const float*)d_in[16];
    const float* res_W1b   = (const float*)d_in[17];
    const float* res_b1b   = (const float*)d_in[18];
    const float* res_W2b   = (const float*)d_in[19];
    const float* res_b2b   = (const float*)d_in[20];
    float* out = (float*)d_out;

    static bool attr_set = false;
    if (!attr_set) {
        cudaFuncSetAttribute(k_edge, cudaFuncAttributeMaxDynamicSharedMemorySize, 146 * 1024);
        attr_set = true;
    }

    k_zero<<<1024, 256>>>();
    k_gemm_pq<<<dim3((N_EDGES + 63) / 64, 2), 256>>>(nbr_fea, W_full);
    k_gemm_angle<<<N_ANGLES / 64, 256>>>(angle_fea, W_full, nidx, cai);
    k_finalize<<<N_CRYST, 256>>>(cn_gamma, cn_beta);
    k_msg<<<N_ANGLES / 8, 256>>>(cai, nidx, W_mask, ln_core_g, ln_core_b);
    k_edge<<<148, 256, 36480 * sizeof(float)>>>(nbr_fea, ln2_g, ln2_b,
                                                res_W1a, res_b1a, res_W2a, res_b2a,
                                                res_W1b, res_b1b, res_W2b, res_b2b, out);
}

// round 4
// speedup vs baseline: 1.5222x; 1.1801x over previous
#include <cuda_runtime.h>
#include <cuda_fp16.h>
#include <cstdint>

#define N_EDGES 100000
#define N_ANGLES 400000
#define N_CRYST 512
#define EPS 1e-5f
#define INV_SQRT_2 0.70710678118654752440f

typedef unsigned long long ull;

// ---------- scratch (static device globals; no runtime allocation) ----------
__device__ __half g_PQh[(size_t)N_EDGES * 512];   // P | Q  (fp16 storage)
__device__ __half g_hh[(size_t)N_ANGLES * 256];   // h      (fp16 storage)
__device__ float g_sum[N_CRYST * 256];
__device__ float g_sumsq[N_CRYST * 256];
__device__ int   g_cnt[N_CRYST];
__device__ float g_ca[N_CRYST * 256];
__device__ float g_cb[N_CRYST * 256];
__device__ float g_s[(size_t)N_EDGES * 128];
__device__ int   g_ecnt[N_EDGES];

__device__ __forceinline__ ull pack2(float a, float b) {
    ull r; asm("mov.b64 %0, {%1, %2};" : "=l"(r) : "f"(a), "f"(b)); return r;
}
__device__ __forceinline__ void unpack2(ull v, float& a, float& b) {
    asm("mov.b64 {%0, %1}, %2;" : "=f"(a), "=f"(b) : "l"(v));
}
__device__ __forceinline__ ull fma2(ull a, ull b, ull c) {
    ull d; asm("fma.rn.f32x2 %0, %1, %2, %3;" : "=l"(d) : "l"(a), "l"(b), "l"(c)); return d;
}
__device__ __forceinline__ float silu_f(float x) { return x / (1.f + __expf(-x)); }

// ---------- K0: zero scratch ----------
__global__ void k_zero() {
    size_t i = (size_t)blockIdx.x * blockDim.x + threadIdx.x;
    size_t stride = (size_t)gridDim.x * blockDim.x;
    for (size_t t = i; t < (size_t)N_EDGES * 128; t += stride) g_s[t] = 0.f;
    for (size_t t = i; t < (size_t)N_EDGES; t += stride) g_ecnt[t] = 0;
    for (size_t t = i; t < (size_t)N_CRYST * 256; t += stride) { g_sum[t] = 0.f; g_sumsq[t] = 0.f; }
    for (size_t t = i; t < (size_t)N_CRYST; t += stride) g_cnt[t] = 0;
}

// ---------- shared GEMM body: 64x256 block tile, 8x8 per thread, FFMA2 ------
struct GemmSmem { float a[32][64]; float w[32][256]; };

__device__ __forceinline__ void gemm_tile_mm(GemmSmem& sm, int m0, int n0, ull acc2[8][4]) {
#pragma unroll
    for (int k = 0; k < 32; k++) {
        float4 A0 = *reinterpret_cast<float4*>(&sm.a[k][m0]);
        float4 A1 = *reinterpret_cast<float4*>(&sm.a[k][m0 + 4]);
        ull w2[4];
        w2[0] = *reinterpret_cast<ull*>(&sm.w[k][n0]);
        w2[1] = *reinterpret_cast<ull*>(&sm.w[k][n0 + 2]);
        w2[2] = *reinterpret_cast<ull*>(&sm.w[k][n0 + 4]);
        w2[3] = *reinterpret_cast<ull*>(&sm.w[k][n0 + 6]);
        float av[8] = {A0.x, A0.y, A0.z, A0.w, A1.x, A1.y, A1.z, A1.w};
#pragma unroll
        for (int i = 0; i < 8; i++) {
            ull a2 = pack2(av[i], av[i]);
#pragma unroll
            for (int j = 0; j < 4; j++) acc2[i][j] = fma2(a2, w2[j], acc2[i][j]);
        }
    }
}

// ---------- K1a: P/Q = nbr_fea @ W[:,64:192].T / W[:,192:320].T -------------
__global__ __launch_bounds__(256) void k_gemm_pq(const float* __restrict__ nbr,
                                                 const float* __restrict__ W) {
    __shared__ GemmSmem sm;
    int tid = threadIdx.x;
    int tx = tid & 31, ty = tid >> 5;
    int m0 = ty * 8, n0 = tx * 8;
    int m_base = blockIdx.x * 64;
    int koff = 64 + (int)blockIdx.y * 128;

    ull acc2[8][4];
#pragma unroll
    for (int i = 0; i < 8; i++)
#pragma unroll
        for (int j = 0; j < 4; j++) acc2[i][j] = 0ull;

    for (int kc = 0; kc < 4; kc++) {
        int k0 = kc * 32;
#pragma unroll
        for (int it = 0; it < 2; it++) {
            int lin = tid * 2 + it;
            int r = lin >> 3, q = lin & 7;
            int grow = m_base + r; if (grow >= N_EDGES) grow = N_EDGES - 1;
            float4 v = *reinterpret_cast<const float4*>(nbr + (size_t)grow * 128 + k0 + q * 4);
            sm.a[q * 4 + 0][r] = v.x; sm.a[q * 4 + 1][r] = v.y;
            sm.a[q * 4 + 2][r] = v.z; sm.a[q * 4 + 3][r] = v.w;
        }
#pragma unroll
        for (int it = 0; it < 8; it++) {
            int lin = it * 256 + tid;
            int n = lin >> 3, q = lin & 7;
            float4 v = *reinterpret_cast<const float4*>(W + (size_t)n * 320 + koff + k0 + q * 4);
            sm.w[q * 4 + 0][n] = v.x; sm.w[q * 4 + 1][n] = v.y;
            sm.w[q * 4 + 2][n] = v.z; sm.w[q * 4 + 3][n] = v.w;
        }
        __syncthreads();
        gemm_tile_mm(sm, m0, n0, acc2);
        __syncthreads();
    }
    int colbase = (int)blockIdx.y * 256 + n0;
#pragma unroll
    for (int i = 0; i < 8; i++) {
        int grow = m_base + m0 + i;
        if (grow < N_EDGES) {
            float o[8];
#pragma unroll
            for (int j = 0; j < 4; j++) unpack2(acc2[i][j], o[2 * j], o[2 * j + 1]);
            __half2 hh[4];
#pragma unroll
            for (int j = 0; j < 4; j++) hh[j] = __floats2half2_rn(o[2 * j], o[2 * j + 1]);
            *reinterpret_cast<uint4*>(&g_PQh[(size_t)grow * 512 + colbase]) =
                *reinterpret_cast<uint4*>(hh);
        }
    }
}

// ---------- K1b: h = angle@Wa.T + P[i0] + Q[i1], FUSED crystal stats --------
__global__ __launch_bounds__(256) void k_gemm_angle(const float* __restrict__ ang,
                                                    const float* __restrict__ W,
                                                    const int* __restrict__ nidx,
                                                    const int* __restrict__ seg) {
    __shared__ GemmSmem sm;
    __shared__ float sum_sm[2][256];
    __shared__ float sq_sm[2][256];
    __shared__ int cnt_sm[2];
    __shared__ int seg_sm[64];

    int tid = threadIdx.x;
    int tx = tid & 31, ty = tid >> 5;
    int m0 = ty * 8, n0 = tx * 8;
    int m_base = blockIdx.x * 64;

    sum_sm[0][tid] = 0.f; sum_sm[1][tid] = 0.f;
    sq_sm[0][tid] = 0.f;  sq_sm[1][tid] = 0.f;
    if (tid < 2) cnt_sm[tid] = 0;
    if (tid < 64) seg_sm[tid] = seg[m_base + tid];

    ull acc2[8][4];
#pragma unroll
    for (int i = 0; i < 8; i++)
#pragma unroll
        for (int j = 0; j < 4; j++) acc2[i][j] = 0ull;

    for (int kc = 0; kc < 2; kc++) {
        int k0 = kc * 32;
#pragma unroll
        for (int it = 0; it < 2; it++) {
            int lin = tid * 2 + it;
            int r = lin >> 3, q = lin & 7;
            float4 v = *reinterpret_cast<const float4*>(ang + (size_t)(m_base + r) * 64 + k0 + q * 4);
            sm.a[q * 4 + 0][r] = v.x; sm.a[q * 4 + 1][r] = v.y;
            sm.a[q * 4 + 2][r] = v.z; sm.a[q * 4 + 3][r] = v.w;
        }
#pragma unroll
        for (int it = 0; it < 8; it++) {
            int lin = it * 256 + tid;
            int n = lin >> 3, q = lin & 7;
            float4 v = *reinterpret_cast<const float4*>(W + (size_t)n * 320 + k0 + q * 4);
            sm.w[q * 4 + 0][n] = v.x; sm.w[q * 4 + 1][n] = v.y;
            sm.w[q * 4 + 2][n] = v.z; sm.w[q * 4 + 3][n] = v.w;
        }
        __syncthreads();
        gemm_tile_mm(sm, m0, n0, acc2);
        __syncthreads();
    }

    int seg_base = seg_sm[0];
    if (tid < 64) {
        int slot = seg_sm[tid] - seg_base;
        if (slot == 0 || slot == 1) atomicAdd(&cnt_sm[slot], 1);
        else atomicAdd(&g_cnt[seg_sm[tid]], 1);
    }

    float accS[8], accQ[8];
#pragma unroll
    for (int j = 0; j < 8; j++) { accS[j] = 0.f; accQ[j] = 0.f; }
    int cur_slot = -1;

#pragma unroll
    for (int i = 0; i < 8; i++) {
        int grow = m_base + m0 + i;
        int i0 = nidx[grow * 2 + 0];
        int i1 = nidx[grow * 2 + 1];
        float o[8];
#pragma unroll
        for (int j = 0; j < 4; j++) unpack2(acc2[i][j], o[2 * j], o[2 * j + 1]);
        // gather fp16 P (row i0, cols n0..n0+7) and Q (row i1, cols 256+n0..)
        uint4 pu = *reinterpret_cast<const uint4*>(&g_PQh[(size_t)i0 * 512 + n0]);
        uint4 qu = *reinterpret_cast<const uint4*>(&g_PQh[(size_t)i1 * 512 + 256 + n0]);
        const __half2* ph = reinterpret_cast<const __half2*>(&pu);
        const __half2* qh = reinterpret_cast<const __half2*>(&qu);
        float vs[8];
        __half2 outh[4];
#pragma unroll
        for (int j = 0; j < 4; j++) {
            float2 p2 = __half22float2(ph[j]);
            float2 q2 = __half22float2(qh[j]);
            float r0 = o[2 * j + 0] + p2.x + q2.x;
            float r1 = o[2 * j + 1] + p2.y + q2.y;
            vs[2 * j] = r0; vs[2 * j + 1] = r1;
            outh[j] = __floats2half2_rn(r0, r1);
        }
        *reinterpret_cast<uint4*>(&g_hh[(size_t)grow * 256 + n0]) =
            *reinterpret_cast<uint4*>(outh);

        int sg = seg_sm[m0 + i];
        int slot = sg - seg_base;
        if (slot == 0 || slot == 1) {
            if (slot != cur_slot) {
                if (cur_slot >= 0) {
#pragma unroll
                    for (int j = 0; j < 8; j++) {
                        atomicAdd(&sum_sm[cur_slot][n0 + j], accS[j]);
                        atomicAdd(&sq_sm[cur_slot][n0 + j], accQ[j]);
                        accS[j] = 0.f; accQ[j] = 0.f;
                    }
                }
                cur_slot = slot;
            }
#pragma unroll
            for (int j = 0; j < 8; j++) { accS[j] += vs[j]; accQ[j] += vs[j] * vs[j]; }
        } else { // fallback (sorted segs should never hit this)
#pragma unroll
            for (int j = 0; j < 8; j++) {
                atomicAdd(&g_sum[sg * 256 + n0 + j], vs[j]);
                atomicAdd(&g_sumsq[sg * 256 + n0 + j], vs[j] * vs[j]);
            }
        }
    }
    if (cur_slot >= 0) {
#pragma unroll
        for (int j = 0; j < 8; j++) {
            atomicAdd(&sum_sm[cur_slot][n0 + j], accS[j]);
            atomicAdd(&sq_sm[cur_slot][n0 + j], accQ[j]);
        }
    }
    __syncthreads();
#pragma unroll
    for (int slot = 0; slot < 2; slot++) {
        int sg = seg_base + slot;
        if (cnt_sm[slot] > 0 && sg < N_CRYST) {
            atomicAdd(&g_sum[sg * 256 + tid], sum_sm[slot][tid]);
            atomicAdd(&g_sumsq[sg * 256 + tid], sq_sm[slot][tid]);
            if (tid == 0) atomicAdd(&g_cnt[sg], cnt_sm[slot]);
        }
    }
}

// ---------- K3: crystal-norm affine coefficients ----------------------------
__global__ void k_finalize(const float* __restrict__ gamma, const float* __restrict__ beta) {
    int c = blockIdx.x, n = threadIdx.x;
    float cnt = fmaxf((float)g_cnt[c], 1.f);
    float mean = g_sum[c * 256 + n] / cnt;
    float var = fmaxf(g_sumsq[c * 256 + n] / cnt - mean * mean, 0.f);
    float a = gamma[n] * rsqrtf(var + EPS);
    g_ca[c * 256 + n] = a;
    g_cb[c * 256 + n] = beta[n] - mean * a;
}

// ---------- K4: per-angle msg + scatter into edge sums (1 warp/angle) -------
__global__ __launch_bounds__(256) void k_msg(const int* __restrict__ seg,
                                             const int* __restrict__ nidx,
                                             const float* __restrict__ Wm,
                                             const float* __restrict__ lng,
                                             const float* __restrict__ lnb) {
    int lane = threadIdx.x & 31;
    int row = blockIdx.x * 8 + (threadIdx.x >> 5);
    const uint2* hr = reinterpret_cast<const uint2*>(&g_hh[(size_t)row * 256]);
    uint2 hcu = hr[lane];        // core: 4 halves
    uint2 hfu = hr[32 + lane];   // filter: 4 halves
    float2 c01 = __half22float2(*reinterpret_cast<__half2*>(&hcu.x));
    float2 c23 = __half22float2(*reinterpret_cast<__half2*>(&hcu.y));
    float2 f01 = __half22float2(*reinterpret_cast<__half2*>(&hfu.x));
    float2 f23 = __half22float2(*reinterpret_cast<__half2*>(&hfu.y));
    float4 hc = {c01.x, c01.y, c23.x, c23.y};
    float4 hf = {f01.x, f01.y, f23.x, f23.y};
    int sg = seg[row];
    const float4* ca = reinterpret_cast<const float4*>(&g_ca[(size_t)sg * 256]);
    const float4* cb = reinterpret_cast<const float4*>(&g_cb[(size_t)sg * 256]);
    float4 ac = ca[lane], af = ca[32 + lane];
    float4 bc = cb[lane], bf = cb[32 + lane];
    float4 core, filt;
    core.x = hc.x * ac.x + bc.x; core.y = hc.y * ac.y + bc.y;
    core.z = hc.z * ac.z + bc.z; core.w = hc.w * ac.w + bc.w;
    filt.x = hf.x * af.x + bf.x; filt.y = hf.y * af.y + bf.y;
    filt.z = hf.z * af.z + bf.z; filt.w = hf.w * af.w + bf.w;
    float s1 = core.x + core.y + core.z + core.w;
    float s2 = core.x * core.x + core.y * core.y + core.z * core.z + core.w * core.w;
#pragma unroll
    for (int off = 16; off >= 1; off >>= 1) {
        s1 += __shfl_xor_sync(0xffffffffu, s1, off);
        s2 += __shfl_xor_sync(0xffffffffu, s2, off);
    }
    float mean = s1 * (1.f / 128.f);
    float var = fmaxf(s2 * (1.f / 128.f) - mean * mean, 0.f);
    float rstd = rsqrtf(var + EPS);
    float4 g4 = reinterpret_cast<const float4*>(lng)[lane];
    float4 b4 = reinterpret_cast<const float4*>(lnb)[lane];
    float4 sl;
    sl.x = silu_f((core.x - mean) * rstd * g4.x + b4.x);
    sl.y = silu_f((core.y - mean) * rstd * g4.y + b4.y);
    sl.z = silu_f((core.z - mean) * rstd * g4.z + b4.z);
    sl.w = silu_f((core.w - mean) * rstd * g4.w + b4.w);
    float4 wm = reinterpret_cast<const float4*>(Wm)[lane];
    float gp = filt.x * wm.x + filt.y * wm.y + filt.z * wm.z + filt.w * wm.w;
#pragma unroll
    for (int off = 16; off >= 1; off >>= 1) gp += __shfl_xor_sync(0xffffffffu, gp, off);
    float gate = 1.f / (1.f + __expf(-gp));
    float4 msg = {gate * sl.x, gate * sl.y, gate * sl.z, gate * sl.w};
    int src = nidx[row * 2];
    float* dst = &g_s[(size_t)src * 128 + lane * 4];
    asm volatile("red.global.add.v4.f32 [%0], {%1,%2,%3,%4};"
                 :: "l"(dst), "f"(msg.x), "f"(msg.y), "f"(msg.z), "f"(msg.w) : "memory");
    if (lane == 0) atomicAdd(&g_ecnt[src], 1);
}

// ---------- K5: per-edge LN2 + two residual MLPs + output -------------------
// 512 threads, 32 edges per group, float4-chunked weight layouts.
__global__ __launch_bounds__(512) void k_edge(const float* __restrict__ nbr,
                       const float* __restrict__ ln2g, const float* __restrict__ ln2b,
                       const float* __restrict__ W1a, const float* __restrict__ b1a,
                       const float* __restrict__ W2a, const float* __restrict__ b2a,
                       const float* __restrict__ W1b, const float* __restrict__ b1b,
                       const float* __restrict__ W2b, const float* __restrict__ b2b,
                       float* __restrict__ out) {
    extern __shared__ float sm[];
    float* W1aT4 = sm;            // [(d>>2)*64 + j]*4 + (d&3)
    float* W2aS4 = sm + 8192;     // [(j>>2)*128 + d]*4 + (j&3)
    float* W1bT4 = sm + 16384;
    float* W2bS4 = sm + 24576;
    float* b1as = sm + 32768;     // 64
    float* b2as = sm + 32832;     // 128
    float* b1bs = sm + 32960;     // 64
    float* b2bs = sm + 33024;     // 128
    float* g2s  = sm + 33152;     // 128
    float* bb2s = sm + 33280;     // 128
    float* x_sm = sm + 33408;     // [32][128]
    float* h1_sm = sm + 37504;    // [32][64]

    int tid = threadIdx.x;
    for (int i = tid; i < 8192; i += 512) {
        int j = i >> 7, d = i & 127;      // W1 is [64][128]: W1[j][d]
        W1aT4[((d >> 2) * 64 + j) * 4 + (d & 3)] = W1a[i];
        W1bT4[((d >> 2) * 64 + j) * 4 + (d & 3)] = W1b[i];
        int d2 = i >> 6, j2 = i & 63;     // W2 is [128][64]: W2[d2][j2]
        W2aS4[((j2 >> 2) * 128 + d2) * 4 + (j2 & 3)] = W2a[i];
        W2bS4[((j2 >> 2) * 128 + d2) * 4 + (j2 & 3)] = W2b[i];
    }
    if (tid < 64) { b1as[tid] = b1a[tid]; b1bs[tid] = b1b[tid]; }
    else if (tid >= 128 && tid < 256) {
        int t = tid - 128;
        b2as[t] = b2a[t]; b2bs[t] = b2b[t]; g2s[t] = ln2g[t]; bb2s[t] = ln2b[t];
    }
    __syncthreads();

    for (int grp = blockIdx.x; grp < N_EDGES / 32; grp += gridDim.x) {
        int e_base = grp * 32;
        { // Phase A: mean-msg + LN2 -> x_sm (32 edges x 16 threads)
            int eL = tid >> 4, l16 = tid & 15;
            int e = e_base + eL;
            float inv = 1.f / fmaxf((float)g_ecnt[e], 1.f);
            const float4* sp = reinterpret_cast<const float4*>(&g_s[(size_t)e * 128]);
            float4 v0 = sp[l16 * 2], v1 = sp[l16 * 2 + 1];
            float vals[8] = {v0.x * inv, v0.y * inv, v0.z * inv, v0.w * inv,
                             v1.x * inv, v1.y * inv, v1.z * inv, v1.w * inv};
            float s1 = 0.f, s2 = 0.f;
#pragma unroll
            for (int k = 0; k < 8; k++) { s1 += vals[k]; s2 += vals[k] * vals[k]; }
#pragma unroll
            for (int off = 8; off >= 1; off >>= 1) {
                s1 += __shfl_xor_sync(0xffffffffu, s1, off);
                s2 += __shfl_xor_sync(0xffffffffu, s2, off);
            }
            float mean = s1 * (1.f / 128.f);
            float var = fmaxf(s2 * (1.f / 128.f) - mean * mean, 0.f);
            float rstd = rsqrtf(var + EPS);
            int d0 = l16 * 8;
#pragma unroll
            for (int k = 0; k < 8; k++)
                x_sm[eL * 128 + d0 + k] = (vals[k] - mean) * rstd * g2s[d0 + k] + bb2s[d0 + k];
        }
        __syncthreads();
        { // MLP A hidden: j=0..63, g=0..7 (4 edges each)
            int j = tid & 63, g = tid >> 6;
            float a0 = b1as[j], a1 = a0, a2 = a0, a3 = a0;
            const float* xb = &x_sm[(g * 4) * 128];
#pragma unroll 8
            for (int d = 0; d < 128; d += 4) {
                float4 w = *reinterpret_cast<const float4*>(&W1aT4[((d >> 2) * 64 + j) * 4]);
                float4 x0 = *reinterpret_cast<const float4*>(&xb[0 * 128 + d]);
                float4 x1 = *reinterpret_cast<const float4*>(&xb[1 * 128 + d]);
                float4 x2 = *reinterpret_cast<const float4*>(&xb[2 * 128 + d]);
                float4 x3 = *reinterpret_cast<const float4*>(&xb[3 * 128 + d]);
                a0 += x0.x * w.x + x0.y * w.y + x0.z * w.z + x0.w * w.w;
                a1 += x1.x * w.x + x1.y * w.y + x1.z * w.z + x1.w * w.w;
                a2 += x2.x * w.x + x2.y * w.y + x2.z * w.z + x2.w * w.w;
                a3 += x3.x * w.x + x3.y * w.y + x3.z * w.z + x3.w * w.w;
            }
            h1_sm[(g * 4 + 0) * 64 + j] = silu_f(a0);
            h1_sm[(g * 4 + 1) * 64 + j] = silu_f(a1);
            h1_sm[(g * 4 + 2) * 64 + j] = silu_f(a2);
            h1_sm[(g * 4 + 3) * 64 + j] = silu_f(a3);
        }
        __syncthreads();
        { // MLP A out + residual: d=0..127, gg=0..3 (8 edges each)
            int d = tid & 127, gg = tid >> 7;
            float acc[8];
#pragma unroll
            for (int e = 0; e < 8; e++) acc[e] = b2as[d];
#pragma unroll 8
            for (int j = 0; j < 64; j += 4) {
                float4 w = *reinterpret_cast<const float4*>(&W2aS4[((j >> 2) * 128 + d) * 4]);
#pragma unroll
                for (int e = 0; e < 8; e++) {
                    float4 h = *reinterpret_cast<const float4*>(&h1_sm[(gg * 8 + e) * 64 + j]);
                    acc[e] += h.x * w.x + h.y * w.y + h.z * w.z + h.w * w.w;
                }
            }
#pragma unroll
            for (int e = 0; e < 8; e++) x_sm[(gg * 8 + e) * 128 + d] += acc[e];
        }
        __syncthreads();
        { // MLP B hidden
            int j = tid & 63, g = tid >> 6;
            float a0 = b1bs[j], a1 = a0, a2 = a0, a3 = a0;
            const float* xb = &x_sm[(g * 4) * 128];
#pragma unroll 8
            for (int d = 0; d < 128; d += 4) {
                float4 w = *reinterpret_cast<const float4*>(&W1bT4[((d >> 2) * 64 + j) * 4]);
                float4 x0 = *reinterpret_cast<const float4*>(&xb[0 * 128 + d]);
                float4 x1 = *reinterpret_cast<const float4*>(&xb[1 * 128 + d]);
                float4 x2 = *reinterpret_cast<const float4*>(&xb[2 * 128 + d]);
                float4 x3 = *reinterpret_cast<const float4*>(&xb[3 * 128 + d]);
                a0 += x0.x * w.x + x0.y * w.y + x0.z * w.z + x0.w * w.w;
                a1 += x1.x * w.x + x1.y * w.y + x1.z * w.z + x1.w * w.w;
                a2 += x2.x * w.x + x2.y * w.y + x2.z * w.z + x2.w * w.w;
                a3 += x3.x * w.x + x3.y * w.y + x3.z * w.z + x3.w * w.w;
            }
            h1_sm[(g * 4 + 0) * 64 + j] = silu_f(a0);
            h1_sm[(g * 4 + 1) * 64 + j] = silu_f(a1);
            h1_sm[(g * 4 + 2) * 64 + j] = silu_f(a2);
            h1_sm[(g * 4 + 3) * 64 + j] = silu_f(a3);
        }
        __syncthreads();
        { // MLP B out + residual + final output
            int d = tid & 127, gg = tid >> 7;
            float acc[8];
#pragma unroll
            for (int e = 0; e < 8; e++) acc[e] = b2bs[d];
#pragma unroll 8
            for (int j = 0; j < 64; j += 4) {
                float4 w = *reinterpret_cast<const float4*>(&W2bS4[((j >> 2) * 128 + d) * 4]);
#pragma unroll
                for (int e = 0; e < 8; e++) {
                    float4 h = *reinterpret_cast<const float4*>(&h1_sm[(gg * 8 + e) * 64 + j]);
                    acc[e] += h.x * w.x + h.y * w.y + h.z * w.z + h.w * w.w;
                }
            }
#pragma unroll
            for (int e = 0; e < 8; e++) {
                int eg = e_base + gg * 8 + e;
                float xf = x_sm[(gg * 8 + e) * 128 + d] + acc[e];
                out[(size_t)eg * 128 + d] = INV_SQRT_2 * (nbr[(size_t)eg * 128 + d] + xf);
            }
        }
        __syncthreads();
    }
}

// ---------- launch ----------------------------------------------------------
extern "C" void kernel_launch(void* const* d_in, const int* in_sizes, int n_in,
                              void* d_out, int out_size) {
    const float* nbr_fea   = (const float*)d_in[0];
    const float* angle_fea = (const float*)d_in[1];
    const int*   nidx      = (const int*)d_in[2];
    const int*   cai       = (const int*)d_in[4];
    const float* W_full    = (const float*)d_in[5];
    const float* W_mask    = (const float*)d_in[6];
    const float* cn_gamma  = (const float*)d_in[7];
    const float* cn_beta   = (const float*)d_in[8];
    const float* ln_core_g = (const float*)d_in[9];
    const float* ln_core_b = (const float*)d_in[10];
    const float* ln2_g     = (const float*)d_in[11];
    const float* ln2_b     = (const float*)d_in[12];
    const float* res_W1a   = (const float*)d_in[13];
    const float* res_b1a   = (const float*)d_in[14];
    const float* res_W2a   = (const float*)d_in[15];
    const float* res_b2a   = (const float*)d_in[16];
    const float* res_W1b   = (const float*)d_in[17];
    const float* res_b1b   = (const float*)d_in[18];
    const float* res_W2b   = (const float*)d_in[19];
    const float* res_b2b   = (const float*)d_in[20];
    float* out = (float*)d_out;

    static bool attr_set = false;
    if (!attr_set) {
        cudaFuncSetAttribute(k_edge, cudaFuncAttributeMaxDynamicSharedMemorySize, 164 * 1024);
        attr_set = true;
    }

    k_zero<<<1024, 256>>>();
    k_gemm_pq<<<dim3((N_EDGES + 63) / 64, 2), 256>>>(nbr_fea, W_full);
    k_gemm_angle<<<N_ANGLES / 64, 256>>>(angle_fea, W_full, nidx, cai);
    k_finalize<<<N_CRYST, 256>>>(cn_gamma, cn_beta);
    k_msg<<<N_ANGLES / 8, 256>>>(cai, nidx, W_mask, ln_core_g, ln_core_b);
    k_edge<<<148, 512, 39552 * sizeof(float)>>>(nbr_fea, ln2_g, ln2_b,
                                                res_W1a, res_b1a, res_W2a, res_b2a,
                                                res_W1b, res_b1b, res_W2b, res_b2b, out);
}

// round 6
// speedup vs baseline: 1.9127x; 1.2565x over previous
#include <cuda_runtime.h>
#include <cuda_fp16.h>
#include <cstdint>

#define N_EDGES 100000
#define N_ANGLES 400000
#define N_CRYST 512
#define EPS 1e-5f
#define INV_SQRT_2 0.70710678118654752440f

typedef unsigned long long ull;
typedef unsigned int uint;

// ---------- scratch (static device globals; no runtime allocation) ----------
__device__ __half g_PQh[(size_t)N_EDGES * 512];   // P | Q  (fp16 storage)
__device__ __half g_hh[(size_t)N_ANGLES * 256];   // h      (fp16 storage)
__device__ float g_sum[N_CRYST * 256];
__device__ float g_sumsq[N_CRYST * 256];
__device__ int   g_cnt[N_CRYST];
__device__ float g_ca[N_CRYST * 256];
__device__ float g_cb[N_CRYST * 256];
__device__ float g_s[(size_t)N_EDGES * 128];
__device__ int   g_ecnt[N_EDGES];

__device__ __forceinline__ float silu_f(float x) { return x / (1.f + __expf(-x)); }
__device__ __forceinline__ uint tf32u(float x) {
    uint u; asm("cvt.rna.tf32.f32 %0, %1;" : "=r"(u) : "f"(x)); return u;
}
__device__ __forceinline__ void mma_tf32(float d[4], const uint a[4], const uint b[2]) {
    asm volatile(
        "mma.sync.aligned.m16n8k8.row.col.f32.tf32.tf32.f32 "
        "{%0,%1,%2,%3},{%4,%5,%6,%7},{%8,%9},{%0,%1,%2,%3};"
        : "+f"(d[0]), "+f"(d[1]), "+f"(d[2]), "+f"(d[3])
        : "r"(a[0]), "r"(a[1]), "r"(a[2]), "r"(a[3]), "r"(b[0]), "r"(b[1]));
}

// ---------- K0: zero scratch ----------
__global__ void k_zero() {
    size_t i = (size_t)blockIdx.x * blockDim.x + threadIdx.x;
    size_t stride = (size_t)gridDim.x * blockDim.x;
    for (size_t t = i; t < (size_t)N_EDGES * 128; t += stride) g_s[t] = 0.f;
    for (size_t t = i; t < (size_t)N_EDGES; t += stride) g_ecnt[t] = 0;
    for (size_t t = i; t < (size_t)N_CRYST * 256; t += stride) { g_sum[t] = 0.f; g_sumsq[t] = 0.f; }
    for (size_t t = i; t < (size_t)N_CRYST; t += stride) g_cnt[t] = 0;
}

// ============ tf32 MMA GEMM: BM=128, BN=128, BK=32, 256 thr (8 warps 4x2) ===
// smem staged in fragment-major order (per PTX m16n8k8 lane mapping):
//   A elem (R,C): mt=R/16, kt=C/8 ; lane=(R%8)*4+(C%4) ; slot=(R%16)/8 + 2*((C%8)/4)
//   B elem (N,C): nt=N/8,  kt=C/8 ; lane=(N%8)*4+(C%4) ; slot=(C%8)/4
struct MmaSmem { uint a[128 * 32]; uint b[128 * 32]; };  // 32 KB

__device__ __forceinline__ void stage_a_elem(uint* a_sm, int row, int C, float v) {
    int mt = row >> 4, r = row & 15, kt = C >> 3, c = C & 7;
    int lane = (r & 7) * 4 + (c & 3);
    int slot = (r >> 3) + 2 * (c >> 2);
    a_sm[(((mt * 4) + kt) * 32 + lane) * 4 + slot] = tf32u(v);
}
__device__ __forceinline__ void stage_b_elem(uint* b_sm, int nrow, int C, float v) {
    int nt = nrow >> 3, n = nrow & 7, kt = C >> 3, c = C & 7;
    int lane = n * 4 + (c & 3);
    int slot = c >> 2;
    b_sm[(((nt * 4) + kt) * 32 + lane) * 2 + slot] = tf32u(v);
}

__device__ __forceinline__ void mma_chunk(MmaSmem& sm, int wm, int wn, int lane,
                                          float acc[2][8][4]) {
#pragma unroll
    for (int kt = 0; kt < 4; kt++) {
        uint4 a0u = *reinterpret_cast<uint4*>(&sm.a[(((wm * 2 + 0) * 4 + kt) * 32 + lane) * 4]);
        uint4 a1u = *reinterpret_cast<uint4*>(&sm.a[(((wm * 2 + 1) * 4 + kt) * 32 + lane) * 4]);
        uint a0[4] = {a0u.x, a0u.y, a0u.z, a0u.w};
        uint a1[4] = {a1u.x, a1u.y, a1u.z, a1u.w};
#pragma unroll
        for (int j = 0; j < 8; j++) {
            uint2 bu = *reinterpret_cast<uint2*>(&sm.b[(((wn * 8 + j) * 4 + kt) * 32 + lane) * 2]);
            uint b[2] = {bu.x, bu.y};
            mma_tf32(acc[0][j], a0, b);
            mma_tf32(acc[1][j], a1, b);
        }
    }
}

// ---------- K1a: P/Q = nbr_fea @ W[:,64:192].T / W[:,192:320].T -------------
// grid: (ceil(M/128), 4) ; y: bit0 = n-half (0..127 vs 128..255), bit1 = P/Q
__global__ __launch_bounds__(256) void k_gemm_pq(const float* __restrict__ nbr,
                                                 const float* __restrict__ W) {
    __shared__ MmaSmem sm;
    int tid = threadIdx.x;
    int warp = tid >> 5, lane = tid & 31;
    int wm = warp >> 1, wn = warp & 1;
    int m_base = blockIdx.x * 128;
    int nb = blockIdx.y & 1, qsel = blockIdx.y >> 1;
    int koff = 64 + qsel * 128;
    int n_base = nb * 128;

    float acc[2][8][4];
#pragma unroll
    for (int i = 0; i < 2; i++)
#pragma unroll
        for (int j = 0; j < 8; j++)
#pragma unroll
            for (int k = 0; k < 4; k++) acc[i][j][k] = 0.f;

    for (int kc = 0; kc < 4; kc++) {
        int k0 = kc * 32;
        // stage A: 128x32
#pragma unroll
        for (int it = 0; it < 4; it++) {
            int lin = it * 256 + tid;
            int row = lin >> 3, c4 = (lin & 7) * 4;
            int grow = m_base + row; if (grow >= N_EDGES) grow = N_EDGES - 1;
            float4 v = *reinterpret_cast<const float4*>(nbr + (size_t)grow * 128 + k0 + c4);
            stage_a_elem(sm.a, row, c4 + 0, v.x);
            stage_a_elem(sm.a, row, c4 + 1, v.y);
            stage_a_elem(sm.a, row, c4 + 2, v.z);
            stage_a_elem(sm.a, row, c4 + 3, v.w);
        }
        // stage B: 128x32 from W rows n_base.., cols koff+k0..
#pragma unroll
        for (int it = 0; it < 4; it++) {
            int lin = it * 256 + tid;
            int row = lin >> 3, c4 = (lin & 7) * 4;
            float4 v = *reinterpret_cast<const float4*>(W + (size_t)(n_base + row) * 320 + koff + k0 + c4);
            stage_b_elem(sm.b, row, c4 + 0, v.x);
            stage_b_elem(sm.b, row, c4 + 1, v.y);
            stage_b_elem(sm.b, row, c4 + 2, v.z);
            stage_b_elem(sm.b, row, c4 + 3, v.w);
        }
        __syncthreads();
        mma_chunk(sm, wm, wn, lane, acc);
        __syncthreads();
    }
    // epilogue -> fp16 g_PQh
    int r = lane >> 2, cq = lane & 3;
#pragma unroll
    for (int mi = 0; mi < 2; mi++) {
        int R0 = m_base + wm * 32 + mi * 16 + r;
        int R1 = R0 + 8;
#pragma unroll
        for (int j = 0; j < 8; j++) {
            int gcol = qsel * 256 + n_base + wn * 64 + j * 8 + cq * 2;
            if (R0 < N_EDGES)
                *reinterpret_cast<__half2*>(&g_PQh[(size_t)R0 * 512 + gcol]) =
                    __floats2half2_rn(acc[mi][j][0], acc[mi][j][1]);
            if (R1 < N_EDGES)
                *reinterpret_cast<__half2*>(&g_PQh[(size_t)R1 * 512 + gcol]) =
                    __floats2half2_rn(acc[mi][j][2], acc[mi][j][3]);
        }
    }
}

// ---------- K1b: h = angle@Wa.T + P[i0] + Q[i1] -----------------------------
// grid: (3125, 2) ; y = n-half
__global__ __launch_bounds__(256) void k_gemm_angle(const float* __restrict__ ang,
                                                    const float* __restrict__ W,
                                                    const int* __restrict__ nidx) {
    __shared__ MmaSmem sm;
    __shared__ int i0_sm[128], i1_sm[128];
    int tid = threadIdx.x;
    int warp = tid >> 5, lane = tid & 31;
    int wm = warp >> 1, wn = warp & 1;
    int m_base = blockIdx.x * 128;
    int n_base = blockIdx.y * 128;

    if (tid < 128) {
        i0_sm[tid] = nidx[(m_base + tid) * 2 + 0];
        i1_sm[tid] = nidx[(m_base + tid) * 2 + 1];
    }

    float acc[2][8][4];
#pragma unroll
    for (int i = 0; i < 2; i++)
#pragma unroll
        for (int j = 0; j < 8; j++)
#pragma unroll
            for (int k = 0; k < 4; k++) acc[i][j][k] = 0.f;

    for (int kc = 0; kc < 2; kc++) {
        int k0 = kc * 32;
#pragma unroll
        for (int it = 0; it < 4; it++) {
            int lin = it * 256 + tid;
            int row = lin >> 3, c4 = (lin & 7) * 4;
            float4 v = *reinterpret_cast<const float4*>(ang + (size_t)(m_base + row) * 64 + k0 + c4);
            stage_a_elem(sm.a, row, c4 + 0, v.x);
            stage_a_elem(sm.a, row, c4 + 1, v.y);
            stage_a_elem(sm.a, row, c4 + 2, v.z);
            stage_a_elem(sm.a, row, c4 + 3, v.w);
        }
#pragma unroll
        for (int it = 0; it < 4; it++) {
            int lin = it * 256 + tid;
            int row = lin >> 3, c4 = (lin & 7) * 4;
            float4 v = *reinterpret_cast<const float4*>(W + (size_t)(n_base + row) * 320 + k0 + c4);
            stage_b_elem(sm.b, row, c4 + 0, v.x);
            stage_b_elem(sm.b, row, c4 + 1, v.y);
            stage_b_elem(sm.b, row, c4 + 2, v.z);
            stage_b_elem(sm.b, row, c4 + 3, v.w);
        }
        __syncthreads();
        mma_chunk(sm, wm, wn, lane, acc);
        __syncthreads();
    }
    // epilogue: gather P/Q, add, store fp16 h
    int r = lane >> 2, cq = lane & 3;
#pragma unroll
    for (int mi = 0; mi < 2; mi++) {
        int lr0 = wm * 32 + mi * 16 + r;
        int lr1 = lr0 + 8;
        int R0 = m_base + lr0, R1 = m_base + lr1;
        int i0a = i0_sm[lr0], i1a = i1_sm[lr0];
        int i0b = i0_sm[lr1], i1b = i1_sm[lr1];
#pragma unroll
        for (int j = 0; j < 8; j++) {
            int gcol = n_base + wn * 64 + j * 8 + cq * 2;
            float2 p0 = __half22float2(*reinterpret_cast<const __half2*>(&g_PQh[(size_t)i0a * 512 + gcol]));
            float2 q0 = __half22float2(*reinterpret_cast<const __half2*>(&g_PQh[(size_t)i1a * 512 + 256 + gcol]));
            *reinterpret_cast<__half2*>(&g_hh[(size_t)R0 * 256 + gcol]) =
                __floats2half2_rn(acc[mi][j][0] + p0.x + q0.x, acc[mi][j][1] + p0.y + q0.y);
            float2 p1 = __half22float2(*reinterpret_cast<const __half2*>(&g_PQh[(size_t)i0b * 512 + gcol]));
            float2 q1 = __half22float2(*reinterpret_cast<const __half2*>(&g_PQh[(size_t)i1b * 512 + 256 + gcol]));
            *reinterpret_cast<__half2*>(&g_hh[(size_t)R1 * 256 + gcol]) =
                __floats2half2_rn(acc[mi][j][2] + p1.x + q1.x, acc[mi][j][3] + p1.y + q1.y);
        }
    }
}

// ---------- K2: crystal stats from fp16 h (sorted segments) -----------------
// 3125 blocks x 256 thr: col-pair = tid&127, row-half = tid>>7 (64 rows each)
__global__ __launch_bounds__(256) void k_stats(const int* __restrict__ seg) {
    __shared__ int seg_sm[128];
    int tid = threadIdx.x;
    int bi = blockIdx.x;
    if (tid < 128) seg_sm[tid] = seg[bi * 128 + tid];
    __syncthreads();
    int cp = tid & 127, halfsel = tid >> 7;
    int r0 = halfsel * 64;
    size_t rowbase = (size_t)(bi * 128 + r0);
    int cur = seg_sm[r0];
    float s0 = 0.f, s1 = 0.f, q0 = 0.f, q1 = 0.f; int c = 0;
    for (int r = 0; r < 64; r++) {
        int sg = seg_sm[r0 + r];
        if (sg != cur) {
            atomicAdd(&g_sum[cur * 256 + cp * 2 + 0], s0);
            atomicAdd(&g_sum[cur * 256 + cp * 2 + 1], s1);
            atomicAdd(&g_sumsq[cur * 256 + cp * 2 + 0], q0);
            atomicAdd(&g_sumsq[cur * 256 + cp * 2 + 1], q1);
            if (cp == 0) atomicAdd(&g_cnt[cur], c);
            s0 = s1 = q0 = q1 = 0.f; c = 0; cur = sg;
        }
        float2 v = __half22float2(*reinterpret_cast<const __half2*>(&g_hh[(rowbase + r) * 256 + cp * 2]));
        s0 += v.x; q0 += v.x * v.x;
        s1 += v.y; q1 += v.y * v.y;
        c++;
    }
    atomicAdd(&g_sum[cur * 256 + cp * 2 + 0], s0);
    atomicAdd(&g_sum[cur * 256 + cp * 2 + 1], s1);
    atomicAdd(&g_sumsq[cur * 256 + cp * 2 + 0], q0);
    atomicAdd(&g_sumsq[cur * 256 + cp * 2 + 1], q1);
    if (cp == 0) atomicAdd(&g_cnt[cur], c);
}

// ---------- K3: crystal-norm affine coefficients ----------------------------
__global__ void k_finalize(const float* __restrict__ gamma, const float* __restrict__ beta) {
    int c = blockIdx.x, n = threadIdx.x;
    float cnt = fmaxf((float)g_cnt[c], 1.f);
    float mean = g_sum[c * 256 + n] / cnt;
    float var = fmaxf(g_sumsq[c * 256 + n] / cnt - mean * mean, 0.f);
    float a = gamma[n] * rsqrtf(var + EPS);
    g_ca[c * 256 + n] = a;
    g_cb[c * 256 + n] = beta[n] - mean * a;
}

// ---------- K4: per-angle msg + scatter into edge sums (1 warp/angle) -------
__global__ __launch_bounds__(256) void k_msg(const int* __restrict__ seg,
                                             const int* __restrict__ nidx,
                                             const float* __restrict__ Wm,
                                             const float* __restrict__ lng,
                                             const float* __restrict__ lnb) {
    int lane = threadIdx.x & 31;
    int row = blockIdx.x * 8 + (threadIdx.x >> 5);
    const uint2* hr = reinterpret_cast<const uint2*>(&g_hh[(size_t)row * 256]);
    uint2 hcu = hr[lane];
    uint2 hfu = hr[32 + lane];
    float2 c01 = __half22float2(*reinterpret_cast<__half2*>(&hcu.x));
    float2 c23 = __half22float2(*reinterpret_cast<__half2*>(&hcu.y));
    float2 f01 = __half22float2(*reinterpret_cast<__half2*>(&hfu.x));
    float2 f23 = __half22float2(*reinterpret_cast<__half2*>(&hfu.y));
    float4 hc = {c01.x, c01.y, c23.x, c23.y};
    float4 hf = {f01.x, f01.y, f23.x, f23.y};
    int sg = seg[row];
    const float4* ca = reinterpret_cast<const float4*>(&g_ca[(size_t)sg * 256]);
    const float4* cb = reinterpret_cast<const float4*>(&g_cb[(size_t)sg * 256]);
    float4 ac = ca[lane], af = ca[32 + lane];
    float4 bc = cb[lane], bf = cb[32 + lane];
    float4 core, filt;
    core.x = hc.x * ac.x + bc.x; core.y = hc.y * ac.y + bc.y;
    core.z = hc.z * ac.z + bc.z; core.w = hc.w * ac.w + bc.w;
    filt.x = hf.x * af.x + bf.x; filt.y = hf.y * af.y + bf.y;
    filt.z = hf.z * af.z + bf.z; filt.w = hf.w * af.w + bf.w;
    float s1 = core.x + core.y + core.z + core.w;
    float s2 = core.x * core.x + core.y * core.y + core.z * core.z + core.w * core.w;
#pragma unroll
    for (int off = 16; off >= 1; off >>= 1) {
        s1 += __shfl_xor_sync(0xffffffffu, s1, off);
        s2 += __shfl_xor_sync(0xffffffffu, s2, off);
    }
    float mean = s1 * (1.f / 128.f);
    float var = fmaxf(s2 * (1.f / 128.f) - mean * mean, 0.f);
    float rstd = rsqrtf(var + EPS);
    float4 g4 = reinterpret_cast<const float4*>(lng)[lane];
    float4 b4 = reinterpret_cast<const float4*>(lnb)[lane];
    float4 sl;
    sl.x = silu_f((core.x - mean) * rstd * g4.x + b4.x);
    sl.y = silu_f((core.y - mean) * rstd * g4.y + b4.y);
    sl.z = silu_f((core.z - mean) * rstd * g4.z + b4.z);
    sl.w = silu_f((core.w - mean) * rstd * g4.w + b4.w);
    float4 wm = reinterpret_cast<const float4*>(Wm)[lane];
    float gp = filt.x * wm.x + filt.y * wm.y + filt.z * wm.z + filt.w * wm.w;
#pragma unroll
    for (int off = 16; off >= 1; off >>= 1) gp += __shfl_xor_sync(0xffffffffu, gp, off);
    float gate = 1.f / (1.f + __expf(-gp));
    float4 msg = {gate * sl.x, gate * sl.y, gate * sl.z, gate * sl.w};
    int src = nidx[row * 2];
    float* dst = &g_s[(size_t)src * 128 + lane * 4];
    asm volatile("red.global.add.v4.f32 [%0], {%1,%2,%3,%4};"
                 :: "l"(dst), "f"(msg.x), "f"(msg.y), "f"(msg.z), "f"(msg.w) : "memory");
    if (lane == 0) atomicAdd(&g_ecnt[src], 1);
}

// ---------- K5: per-edge LN2 + two residual MLPs + output -------------------
__global__ __launch_bounds__(512) void k_edge(const float* __restrict__ nbr,
                       const float* __restrict__ ln2g, const float* __restrict__ ln2b,
                       const float* __restrict__ W1a, const float* __restrict__ b1a,
                       const float* __restrict__ W2a, const float* __restrict__ b2a,
                       const float* __restrict__ W1b, const float* __restrict__ b1b,
                       const float* __restrict__ W2b, const float* __restrict__ b2b,
                       float* __restrict__ out) {
    extern __shared__ float sm[];
    float* W1aT4 = sm;
    float* W2aS4 = sm + 8192;
    float* W1bT4 = sm + 16384;
    float* W2bS4 = sm + 24576;
    float* b1as = sm + 32768;
    float* b2as = sm + 32832;
    float* b1bs = sm + 32960;
    float* b2bs = sm + 33024;
    float* g2s  = sm + 33152;
    float* bb2s = sm + 33280;
    float* x_sm = sm + 33408;     // [32][128]
    float* h1_sm = sm + 37504;    // [32][64]

    int tid = threadIdx.x;
    for (int i = tid; i < 8192; i += 512) {
        int j = i >> 7, d = i & 127;
        W1aT4[((d >> 2) * 64 + j) * 4 + (d & 3)] = W1a[i];
        W1bT4[((d >> 2) * 64 + j) * 4 + (d & 3)] = W1b[i];
        int d2 = i >> 6, j2 = i & 63;
        W2aS4[((j2 >> 2) * 128 + d2) * 4 + (j2 & 3)] = W2a[i];
        W2bS4[((j2 >> 2) * 128 + d2) * 4 + (j2 & 3)] = W2b[i];
    }
    if (tid < 64) { b1as[tid] = b1a[tid]; b1bs[tid] = b1b[tid]; }
    else if (tid >= 128 && tid < 256) {
        int t = tid - 128;
        b2as[t] = b2a[t]; b2bs[t] = b2b[t]; g2s[t] = ln2g[t]; bb2s[t] = ln2b[t];
    }
    __syncthreads();

    for (int grp = blockIdx.x; grp < N_EDGES / 32; grp += gridDim.x) {
        int e_base = grp * 32;
        {
            int eL = tid >> 4, l16 = tid & 15;
            int e = e_base + eL;
            float inv = 1.f / fmaxf((float)g_ecnt[e], 1.f);
            const float4* sp = reinterpret_cast<const float4*>(&g_s[(size_t)e * 128]);
            float4 v0 = sp[l16 * 2], v1 = sp[l16 * 2 + 1];
            float vals[8] = {v0.x * inv, v0.y * inv, v0.z * inv, v0.w * inv,
                             v1.x * inv, v1.y * inv, v1.z * inv, v1.w * inv};
            float s1 = 0.f, s2 = 0.f;
#pragma unroll
            for (int k = 0; k < 8; k++) { s1 += vals[k]; s2 += vals[k] * vals[k]; }
#pragma unroll
            for (int off = 8; off >= 1; off >>= 1) {
                s1 += __shfl_xor_sync(0xffffffffu, s1, off);
                s2 += __shfl_xor_sync(0xffffffffu, s2, off);
            }
            float mean = s1 * (1.f / 128.f);
            float var = fmaxf(s2 * (1.f / 128.f) - mean * mean, 0.f);
            float rstd = rsqrtf(var + EPS);
            int d0 = l16 * 8;
#pragma unroll
            for (int k = 0; k < 8; k++)
                x_sm[eL * 128 + d0 + k] = (vals[k] - mean) * rstd * g2s[d0 + k] + bb2s[d0 + k];
        }
        __syncthreads();
        {
            int j = tid & 63, g = tid >> 6;
            float a0 = b1as[j], a1 = a0, a2 = a0, a3 = a0;
            const float* xb = &x_sm[(g * 4) * 128];
#pragma unroll 8
            for (int d = 0; d < 128; d += 4) {
                float4 w = *reinterpret_cast<const float4*>(&W1aT4[((d >> 2) * 64 + j) * 4]);
                float4 x0 = *reinterpret_cast<const float4*>(&xb[0 * 128 + d]);
                float4 x1 = *reinterpret_cast<const float4*>(&xb[1 * 128 + d]);
                float4 x2 = *reinterpret_cast<const float4*>(&xb[2 * 128 + d]);
                float4 x3 = *reinterpret_cast<const float4*>(&xb[3 * 128 + d]);
                a0 += x0.x * w.x + x0.y * w.y + x0.z * w.z + x0.w * w.w;
                a1 += x1.x * w.x + x1.y * w.y + x1.z * w.z + x1.w * w.w;
                a2 += x2.x * w.x + x2.y * w.y + x2.z * w.z + x2.w * w.w;
                a3 += x3.x * w.x + x3.y * w.y + x3.z * w.z + x3.w * w.w;
            }
            h1_sm[(g * 4 + 0) * 64 + j] = silu_f(a0);
            h1_sm[(g * 4 + 1) * 64 + j] = silu_f(a1);
            h1_sm[(g * 4 + 2) * 64 + j] = silu_f(a2);
            h1_sm[(g * 4 + 3) * 64 + j] = silu_f(a3);
        }
        __syncthreads();
        {
            int d = tid & 127, gg = tid >> 7;
            float acc[8];
#pragma unroll
            for (int e = 0; e < 8; e++) acc[e] = b2as[d];
#pragma unroll 8
            for (int j = 0; j < 64; j += 4) {
                float4 w = *reinterpret_cast<const float4*>(&W2aS4[((j >> 2) * 128 + d) * 4]);
#pragma unroll
                for (int e = 0; e < 8; e++) {
                    float4 h = *reinterpret_cast<const float4*>(&h1_sm[(gg * 8 + e) * 64 + j]);
                    acc[e] += h.x * w.x + h.y * w.y + h.z * w.z + h.w * w.w;
                }
            }
#pragma unroll
            for (int e = 0; e < 8; e++) x_sm[(gg * 8 + e) * 128 + d] += acc[e];
        }
        __syncthreads();
        {
            int j = tid & 63, g = tid >> 6;
            float a0 = b1bs[j], a1 = a0, a2 = a0, a3 = a0;
            const float* xb = &x_sm[(g * 4) * 128];
#pragma unroll 8
            for (int d = 0; d < 128; d += 4) {
                float4 w = *reinterpret_cast<const float4*>(&W1bT4[((d >> 2) * 64 + j) * 4]);
                float4 x0 = *reinterpret_cast<const float4*>(&xb[0 * 128 + d]);
                float4 x1 = *reinterpret_cast<const float4*>(&xb[1 * 128 + d]);
                float4 x2 = *reinterpret_cast<const float4*>(&xb[2 * 128 + d]);
                float4 x3 = *reinterpret_cast<const float4*>(&xb[3 * 128 + d]);
                a0 += x0.x * w.x + x0.y * w.y + x0.z * w.z + x0.w * w.w;
                a1 += x1.x * w.x + x1.y * w.y + x1.z * w.z + x1.w * w.w;
                a2 += x2.x * w.x + x2.y * w.y + x2.z * w.z + x2.w * w.w;
                a3 += x3.x * w.x + x3.y * w.y + x3.z * w.z + x3.w * w.w;
            }
            h1_sm[(g * 4 + 0) * 64 + j] = silu_f(a0);
            h1_sm[(g * 4 + 1) * 64 + j] = silu_f(a1);
            h1_sm[(g * 4 + 2) * 64 + j] = silu_f(a2);
            h1_sm[(g * 4 + 3) * 64 + j] = silu_f(a3);
        }
        __syncthreads();
        {
            int d = tid & 127, gg = tid >> 7;
            float acc[8];
#pragma unroll
            for (int e = 0; e < 8; e++) acc[e] = b2bs[d];
#pragma unroll 8
            for (int j = 0; j < 64; j += 4) {
                float4 w = *reinterpret_cast<const float4*>(&W2bS4[((j >> 2) * 128 + d) * 4]);
#pragma unroll
                for (int e = 0; e < 8; e++) {
                    float4 h = *reinterpret_cast<const float4*>(&h1_sm[(gg * 8 + e) * 64 + j]);
                    acc[e] += h.x * w.x + h.y * w.y + h.z * w.z + h.w * w.w;
                }
            }
#pragma unroll
            for (int e = 0; e < 8; e++) {
                int eg = e_base + gg * 8 + e;
                float xf = x_sm[(gg * 8 + e) * 128 + d] + acc[e];
                out[(size_t)eg * 128 + d] = INV_SQRT_2 * (nbr[(size_t)eg * 128 + d] + xf);
            }
        }
        __syncthreads();
    }
}

// ---------- launch ----------------------------------------------------------
extern "C" void kernel_launch(void* const* d_in, const int* in_sizes, int n_in,
                              void* d_out, int out_size) {
    const float* nbr_fea   = (const float*)d_in[0];
    const float* angle_fea = (const float*)d_in[1];
    const int*   nidx      = (const int*)d_in[2];
    const int*   cai       = (const int*)d_in[4];
    const float* W_full    = (const float*)d_in[5];
    const float* W_mask    = (const float*)d_in[6];
    const float* cn_gamma  = (const float*)d_in[7];
    const float* cn_beta   = (const float*)d_in[8];
    const float* ln_core_g = (const float*)d_in[9];
    const float* ln_core_b = (const float*)d_in[10];
    const float* ln2_g     = (const float*)d_in[11];
    const float* ln2_b     = (const float*)d_in[12];
    const float* res_W1a   = (const float*)d_in[13];
    const float* res_b1a   = (const float*)d_in[14];
    const float* res_W2a   = (const float*)d_in[15];
    const float* res_b2a   = (const float*)d_in[16];
    const float* res_W1b   = (const float*)d_in[17];
    const float* res_b1b   = (const float*)d_in[18];
    const float* res_W2b   = (const float*)d_in[19];
    const float* res_b2b   = (const float*)d_in[20];
    float* out = (float*)d_out;

    static bool attr_set = false;
    if (!attr_set) {
        cudaFuncSetAttribute(k_edge, cudaFuncAttributeMaxDynamicSharedMemorySize, 164 * 1024);
        attr_set = true;
    }

    k_zero<<<1024, 256>>>();
    k_gemm_pq<<<dim3((N_EDGES + 127) / 128, 4), 256>>>(nbr_fea, W_full);
    k_gemm_angle<<<dim3(N_ANGLES / 128, 2), 256>>>(angle_fea, W_full, nidx);
    k_stats<<<N_ANGLES / 128, 256>>>(cai);
    k_finalize<<<N_CRYST, 256>>>(cn_gamma, cn_beta);
    k_msg<<<N_ANGLES / 8, 256>>>(cai, nidx, W_mask, ln_core_g, ln_core_b);
    k_edge<<<148, 512, 39552 * sizeof(float)>>>(nbr_fea, ln2_g, ln2_b,
                                                res_W1a, res_b1a, res_W2a, res_b2a,
                                                res_W1b, res_b1b, res_W2b, res_b2b, out);
}

// round 7
// speedup vs baseline: 2.3443x; 1.2257x over previous
#include <cuda_runtime.h>
#include <cuda_fp16.h>
#include <cstdint>

#define N_EDGES 100000
#define N_ANGLES 400000
#define N_CRYST 512
#define EPS 1e-5f
#define INV_SQRT_2 0.70710678118654752440f

typedef unsigned long long ull;
typedef unsigned int uint;

// ---------- scratch (static device globals; no runtime allocation) ----------
__device__ __half g_PQh[(size_t)N_EDGES * 512];   // P | Q  (fp16 storage)
__device__ __half g_hh[(size_t)N_ANGLES * 256];   // h      (fp16 storage)
__device__ float g_sum[N_CRYST * 256];
__device__ float g_sumsq[N_CRYST * 256];
__device__ int   g_cnt[N_CRYST];
__device__ float g_ca[N_CRYST * 256];
__device__ float g_cb[N_CRYST * 256];
__device__ float g_s[(size_t)N_EDGES * 128];
__device__ int   g_ecnt[N_EDGES];

__device__ __forceinline__ float silu_f(float x) { return x / (1.f + __expf(-x)); }
__device__ __forceinline__ uint tf32u(float x) {
    uint u; asm("cvt.rna.tf32.f32 %0, %1;" : "=r"(u) : "f"(x)); return u;
}
__device__ __forceinline__ void mma_tf32(float d[4], const uint a[4], const uint b[2]) {
    asm volatile(
        "mma.sync.aligned.m16n8k8.row.col.f32.tf32.tf32.f32 "
        "{%0,%1,%2,%3},{%4,%5,%6,%7},{%8,%9},{%0,%1,%2,%3};"
        : "+f"(d[0]), "+f"(d[1]), "+f"(d[2]), "+f"(d[3])
        : "r"(a[0]), "r"(a[1]), "r"(a[2]), "r"(a[3]), "r"(b[0]), "r"(b[1]));
}

// ---------- K0: zero scratch ----------
__global__ void k_zero() {
    size_t i = (size_t)blockIdx.x * blockDim.x + threadIdx.x;
    size_t stride = (size_t)gridDim.x * blockDim.x;
    for (size_t t = i; t < (size_t)N_EDGES * 128; t += stride) g_s[t] = 0.f;
    for (size_t t = i; t < (size_t)N_EDGES; t += stride) g_ecnt[t] = 0;
    for (size_t t = i; t < (size_t)N_CRYST * 256; t += stride) { g_sum[t] = 0.f; g_sumsq[t] = 0.f; }
    for (size_t t = i; t < (size_t)N_CRYST; t += stride) g_cnt[t] = 0;
}

// ---- fragment-major staging helpers (validated layout, generalized KT) -----
__device__ __forceinline__ void stage_a_g(uint* buf, int KT, int row, int C, float v) {
    int mt = row >> 4, r = row & 15, kt = C >> 3, c = C & 7;
    int lane = (r & 7) * 4 + (c & 3);
    int slot = (r >> 3) + 2 * (c >> 2);
    buf[((mt * KT + kt) * 32 + lane) * 4 + slot] = tf32u(v);
}
__device__ __forceinline__ void stage_b_g(uint* buf, int KT, int nrow, int C, float v) {
    int nt = nrow >> 3, n = nrow & 7, kt = C >> 3, c = C & 7;
    int lane = n * 4 + (c & 3);
    int slot = c >> 2;
    buf[((nt * KT + kt) * 32 + lane) * 2 + slot] = tf32u(v);
}

// ============ tf32 MMA GEMM: BM=128, BN=128, BK=32, 256 thr (8 warps 4x2) ===
struct MmaSmem { uint a[128 * 32]; uint b[128 * 32]; };

__device__ __forceinline__ void stage_a_elem(uint* a_sm, int row, int C, float v) {
    stage_a_g(a_sm, 4, row, C, v);
}
__device__ __forceinline__ void stage_b_elem(uint* b_sm, int nrow, int C, float v) {
    stage_b_g(b_sm, 4, nrow, C, v);
}

__device__ __forceinline__ void mma_chunk(MmaSmem& sm, int wm, int wn, int lane,
                                          float acc[2][8][4]) {
#pragma unroll
    for (int kt = 0; kt < 4; kt++) {
        uint4 a0u = *reinterpret_cast<uint4*>(&sm.a[(((wm * 2 + 0) * 4 + kt) * 32 + lane) * 4]);
        uint4 a1u = *reinterpret_cast<uint4*>(&sm.a[(((wm * 2 + 1) * 4 + kt) * 32 + lane) * 4]);
        uint a0[4] = {a0u.x, a0u.y, a0u.z, a0u.w};
        uint a1[4] = {a1u.x, a1u.y, a1u.z, a1u.w};
#pragma unroll
        for (int j = 0; j < 8; j++) {
            uint2 bu = *reinterpret_cast<uint2*>(&sm.b[(((wn * 8 + j) * 4 + kt) * 32 + lane) * 2]);
            uint b[2] = {bu.x, bu.y};
            mma_tf32(acc[0][j], a0, b);
            mma_tf32(acc[1][j], a1, b);
        }
    }
}

// ---------- K1a: P/Q = nbr_fea @ W[:,64:192].T / W[:,192:320].T -------------
__global__ __launch_bounds__(256) void k_gemm_pq(const float* __restrict__ nbr,
                                                 const float* __restrict__ W) {
    __shared__ MmaSmem sm;
    int tid = threadIdx.x;
    int warp = tid >> 5, lane = tid & 31;
    int wm = warp >> 1, wn = warp & 1;
    int m_base = blockIdx.x * 128;
    int nb = blockIdx.y & 1, qsel = blockIdx.y >> 1;
    int koff = 64 + qsel * 128;
    int n_base = nb * 128;

    float acc[2][8][4];
#pragma unroll
    for (int i = 0; i < 2; i++)
#pragma unroll
        for (int j = 0; j < 8; j++)
#pragma unroll
            for (int k = 0; k < 4; k++) acc[i][j][k] = 0.f;

    for (int kc = 0; kc < 4; kc++) {
        int k0 = kc * 32;
#pragma unroll
        for (int it = 0; it < 4; it++) {
            int lin = it * 256 + tid;
            int row = lin >> 3, c4 = (lin & 7) * 4;
            int grow = m_base + row; if (grow >= N_EDGES) grow = N_EDGES - 1;
            float4 v = *reinterpret_cast<const float4*>(nbr + (size_t)grow * 128 + k0 + c4);
            stage_a_elem(sm.a, row, c4 + 0, v.x);
            stage_a_elem(sm.a, row, c4 + 1, v.y);
            stage_a_elem(sm.a, row, c4 + 2, v.z);
            stage_a_elem(sm.a, row, c4 + 3, v.w);
        }
#pragma unroll
        for (int it = 0; it < 4; it++) {
            int lin = it * 256 + tid;
            int row = lin >> 3, c4 = (lin & 7) * 4;
            float4 v = *reinterpret_cast<const float4*>(W + (size_t)(n_base + row) * 320 + koff + k0 + c4);
            stage_b_elem(sm.b, row, c4 + 0, v.x);
            stage_b_elem(sm.b, row, c4 + 1, v.y);
            stage_b_elem(sm.b, row, c4 + 2, v.z);
            stage_b_elem(sm.b, row, c4 + 3, v.w);
        }
        __syncthreads();
        mma_chunk(sm, wm, wn, lane, acc);
        __syncthreads();
    }
    int r = lane >> 2, cq = lane & 3;
#pragma unroll
    for (int mi = 0; mi < 2; mi++) {
        int R0 = m_base + wm * 32 + mi * 16 + r;
        int R1 = R0 + 8;
#pragma unroll
        for (int j = 0; j < 8; j++) {
            int gcol = qsel * 256 + n_base + wn * 64 + j * 8 + cq * 2;
            if (R0 < N_EDGES)
                *reinterpret_cast<__half2*>(&g_PQh[(size_t)R0 * 512 + gcol]) =
                    __floats2half2_rn(acc[mi][j][0], acc[mi][j][1]);
            if (R1 < N_EDGES)
                *reinterpret_cast<__half2*>(&g_PQh[(size_t)R1 * 512 + gcol]) =
                    __floats2half2_rn(acc[mi][j][2], acc[mi][j][3]);
        }
    }
}

// ---------- K1b: h = angle@Wa.T + P[i0] + Q[i1] -----------------------------
__global__ __launch_bounds__(256) void k_gemm_angle(const float* __restrict__ ang,
                                                    const float* __restrict__ W,
                                                    const int* __restrict__ nidx) {
    __shared__ MmaSmem sm;
    __shared__ int i0_sm[128], i1_sm[128];
    int tid = threadIdx.x;
    int warp = tid >> 5, lane = tid & 31;
    int wm = warp >> 1, wn = warp & 1;
    int m_base = blockIdx.x * 128;
    int n_base = blockIdx.y * 128;

    if (tid < 128) {
        i0_sm[tid] = nidx[(m_base + tid) * 2 + 0];
        i1_sm[tid] = nidx[(m_base + tid) * 2 + 1];
    }

    float acc[2][8][4];
#pragma unroll
    for (int i = 0; i < 2; i++)
#pragma unroll
        for (int j = 0; j < 8; j++)
#pragma unroll
            for (int k = 0; k < 4; k++) acc[i][j][k] = 0.f;

    for (int kc = 0; kc < 2; kc++) {
        int k0 = kc * 32;
#pragma unroll
        for (int it = 0; it < 4; it++) {
            int lin = it * 256 + tid;
            int row = lin >> 3, c4 = (lin & 7) * 4;
            float4 v = *reinterpret_cast<const float4*>(ang + (size_t)(m_base + row) * 64 + k0 + c4);
            stage_a_elem(sm.a, row, c4 + 0, v.x);
            stage_a_elem(sm.a, row, c4 + 1, v.y);
            stage_a_elem(sm.a, row, c4 + 2, v.z);
            stage_a_elem(sm.a, row, c4 + 3, v.w);
        }
#pragma unroll
        for (int it = 0; it < 4; it++) {
            int lin = it * 256 + tid;
            int row = lin >> 3, c4 = (lin & 7) * 4;
            float4 v = *reinterpret_cast<const float4*>(W + (size_t)(n_base + row) * 320 + k0 + c4);
            stage_b_elem(sm.b, row, c4 + 0, v.x);
            stage_b_elem(sm.b, row, c4 + 1, v.y);
            stage_b_elem(sm.b, row, c4 + 2, v.z);
            stage_b_elem(sm.b, row, c4 + 3, v.w);
        }
        __syncthreads();
        mma_chunk(sm, wm, wn, lane, acc);
        __syncthreads();
    }
    int r = lane >> 2, cq = lane & 3;
#pragma unroll
    for (int mi = 0; mi < 2; mi++) {
        int lr0 = wm * 32 + mi * 16 + r;
        int lr1 = lr0 + 8;
        int R0 = m_base + lr0, R1 = m_base + lr1;
        int i0a = i0_sm[lr0], i1a = i1_sm[lr0];
        int i0b = i0_sm[lr1], i1b = i1_sm[lr1];
#pragma unroll
        for (int j = 0; j < 8; j++) {
            int gcol = n_base + wn * 64 + j * 8 + cq * 2;
            float2 p0 = __half22float2(*reinterpret_cast<const __half2*>(&g_PQh[(size_t)i0a * 512 + gcol]));
            float2 q0 = __half22float2(*reinterpret_cast<const __half2*>(&g_PQh[(size_t)i1a * 512 + 256 + gcol]));
            *reinterpret_cast<__half2*>(&g_hh[(size_t)R0 * 256 + gcol]) =
                __floats2half2_rn(acc[mi][j][0] + p0.x + q0.x, acc[mi][j][1] + p0.y + q0.y);
            float2 p1 = __half22float2(*reinterpret_cast<const __half2*>(&g_PQh[(size_t)i0b * 512 + gcol]));
            float2 q1 = __half22float2(*reinterpret_cast<const __half2*>(&g_PQh[(size_t)i1b * 512 + 256 + gcol]));
            *reinterpret_cast<__half2*>(&g_hh[(size_t)R1 * 256 + gcol]) =
                __floats2half2_rn(acc[mi][j][2] + p1.x + q1.x, acc[mi][j][3] + p1.y + q1.y);
        }
    }
}

// ---------- K2: crystal stats from fp16 h (sorted segments, MLP=8) ----------
__global__ __launch_bounds__(256) void k_stats(const int* __restrict__ seg) {
    __shared__ int seg_sm[128];
    int tid = threadIdx.x;
    int bi = blockIdx.x;
    if (tid < 128) seg_sm[tid] = seg[bi * 128 + tid];
    __syncthreads();
    int cp = tid & 127, halfsel = tid >> 7;
    int r0 = halfsel * 64;
    size_t rowbase = (size_t)(bi * 128 + r0);
    int cur = seg_sm[r0];
    float s0 = 0.f, s1 = 0.f, q0 = 0.f, q1 = 0.f; int c = 0;
    for (int rb = 0; rb < 64; rb += 8) {
        float2 v[8];
#pragma unroll
        for (int u = 0; u < 8; u++)
            v[u] = __half22float2(*reinterpret_cast<const __half2*>(
                       &g_hh[(rowbase + rb + u) * 256 + cp * 2]));
#pragma unroll
        for (int u = 0; u < 8; u++) {
            int sg = seg_sm[r0 + rb + u];
            if (sg != cur) {
                atomicAdd(&g_sum[cur * 256 + cp * 2 + 0], s0);
                atomicAdd(&g_sum[cur * 256 + cp * 2 + 1], s1);
                atomicAdd(&g_sumsq[cur * 256 + cp * 2 + 0], q0);
                atomicAdd(&g_sumsq[cur * 256 + cp * 2 + 1], q1);
                if (cp == 0) atomicAdd(&g_cnt[cur], c);
                s0 = s1 = q0 = q1 = 0.f; c = 0; cur = sg;
            }
            s0 += v[u].x; q0 += v[u].x * v[u].x;
            s1 += v[u].y; q1 += v[u].y * v[u].y;
            c++;
        }
    }
    atomicAdd(&g_sum[cur * 256 + cp * 2 + 0], s0);
    atomicAdd(&g_sum[cur * 256 + cp * 2 + 1], s1);
    atomicAdd(&g_sumsq[cur * 256 + cp * 2 + 0], q0);
    atomicAdd(&g_sumsq[cur * 256 + cp * 2 + 1], q1);
    if (cp == 0) atomicAdd(&g_cnt[cur], c);
}

// ---------- K3: crystal-norm affine coefficients ----------------------------
__global__ void k_finalize(const float* __restrict__ gamma, const float* __restrict__ beta) {
    int c = blockIdx.x, n = threadIdx.x;
    float cnt = fmaxf((float)g_cnt[c], 1.f);
    float mean = g_sum[c * 256 + n] / cnt;
    float var = fmaxf(g_sumsq[c * 256 + n] / cnt - mean * mean, 0.f);
    float a = gamma[n] * rsqrtf(var + EPS);
    g_ca[c * 256 + n] = a;
    g_cb[c * 256 + n] = beta[n] - mean * a;
}

// ---------- K4: per-angle msg + scatter into edge sums (1 warp/angle) -------
__global__ __launch_bounds__(256) void k_msg(const int* __restrict__ seg,
                                             const int* __restrict__ nidx,
                                             const float* __restrict__ Wm,
                                             const float* __restrict__ lng,
                                             const float* __restrict__ lnb) {
    int lane = threadIdx.x & 31;
    int row = blockIdx.x * 8 + (threadIdx.x >> 5);
    const uint2* hr = reinterpret_cast<const uint2*>(&g_hh[(size_t)row * 256]);
    uint2 hcu = hr[lane];
    uint2 hfu = hr[32 + lane];
    float2 c01 = __half22float2(*reinterpret_cast<__half2*>(&hcu.x));
    float2 c23 = __half22float2(*reinterpret_cast<__half2*>(&hcu.y));
    float2 f01 = __half22float2(*reinterpret_cast<__half2*>(&hfu.x));
    float2 f23 = __half22float2(*reinterpret_cast<__half2*>(&hfu.y));
    float4 hc = {c01.x, c01.y, c23.x, c23.y};
    float4 hf = {f01.x, f01.y, f23.x, f23.y};
    int sg = seg[row];
    const float4* ca = reinterpret_cast<const float4*>(&g_ca[(size_t)sg * 256]);
    const float4* cb = reinterpret_cast<const float4*>(&g_cb[(size_t)sg * 256]);
    float4 ac = ca[lane], af = ca[32 + lane];
    float4 bc = cb[lane], bf = cb[32 + lane];
    float4 core, filt;
    core.x = hc.x * ac.x + bc.x; core.y = hc.y * ac.y + bc.y;
    core.z = hc.z * ac.z + bc.z; core.w = hc.w * ac.w + bc.w;
    filt.x = hf.x * af.x + bf.x; filt.y = hf.y * af.y + bf.y;
    filt.z = hf.z * af.z + bf.z; filt.w = hf.w * af.w + bf.w;
    float s1 = core.x + core.y + core.z + core.w;
    float s2 = core.x * core.x + core.y * core.y + core.z * core.z + core.w * core.w;
#pragma unroll
    for (int off = 16; off >= 1; off >>= 1) {
        s1 += __shfl_xor_sync(0xffffffffu, s1, off);
        s2 += __shfl_xor_sync(0xffffffffu, s2, off);
    }
    float mean = s1 * (1.f / 128.f);
    float var = fmaxf(s2 * (1.f / 128.f) - mean * mean, 0.f);
    float rstd = rsqrtf(var + EPS);
    float4 g4 = reinterpret_cast<const float4*>(lng)[lane];
    float4 b4 = reinterpret_cast<const float4*>(lnb)[lane];
    float4 sl;
    sl.x = silu_f((core.x - mean) * rstd * g4.x + b4.x);
    sl.y = silu_f((core.y - mean) * rstd * g4.y + b4.y);
    sl.z = silu_f((core.z - mean) * rstd * g4.z + b4.z);
    sl.w = silu_f((core.w - mean) * rstd * g4.w + b4.w);
    float4 wm = reinterpret_cast<const float4*>(Wm)[lane];
    float gp = filt.x * wm.x + filt.y * wm.y + filt.z * wm.z + filt.w * wm.w;
#pragma unroll
    for (int off = 16; off >= 1; off >>= 1) gp += __shfl_xor_sync(0xffffffffu, gp, off);
    float gate = 1.f / (1.f + __expf(-gp));
    float4 msg = {gate * sl.x, gate * sl.y, gate * sl.z, gate * sl.w};
    int src = nidx[row * 2];
    float* dst = &g_s[(size_t)src * 128 + lane * 4];
    asm volatile("red.global.add.v4.f32 [%0], {%1,%2,%3,%4};"
                 :: "l"(dst), "f"(msg.x), "f"(msg.y), "f"(msg.z), "f"(msg.w) : "memory");
    if (lane == 0) atomicAdd(&g_ecnt[src], 1);
}

// ---------- K5: per-edge LN2 + two residual MLPs, tf32 tensor cores ---------
// 512 thr (16 warps), 32 edges per group.
// smem units (4B): W1AF 8192 | W2AF 8192 | W1BF 8192 | W2BF 8192 |
//                  XF 4096 | H1F 2048 | XSM 4096 | BIAS 640  => 43648 (170.5 KB)
__global__ __launch_bounds__(512) void k_edge(const float* __restrict__ nbr,
                       const float* __restrict__ ln2g, const float* __restrict__ ln2b,
                       const float* __restrict__ W1a, const float* __restrict__ b1a,
                       const float* __restrict__ W2a, const float* __restrict__ b2a,
                       const float* __restrict__ W1b, const float* __restrict__ b1b,
                       const float* __restrict__ W2b, const float* __restrict__ b2b,
                       float* __restrict__ out) {
    extern __shared__ uint usm[];
    uint* W1AF = usm;
    uint* W2AF = usm + 8192;
    uint* W1BF = usm + 16384;
    uint* W2BF = usm + 24576;
    uint* XF   = usm + 32768;   // A-frags of X: KT=16, 2 m-tiles
    uint* H1F  = usm + 36864;   // A-frags of H: KT=8,  2 m-tiles
    float* x_sm = (float*)(usm + 38912);  // [32][128]
    float* bias = (float*)(usm + 43008);
    float* b1as = bias;          // 64
    float* b2as = bias + 64;     // 128
    float* b1bs = bias + 192;    // 64
    float* b2bs = bias + 256;    // 128
    float* g2s  = bias + 384;    // 128
    float* bb2s = bias + 512;    // 128

    int tid = threadIdx.x;
    int wid = tid >> 5, lane = tid & 31;
    int r = lane >> 2, cq = lane & 3;

    // stage weights once (fragment-major, tf32)
    for (int i = tid; i < 8192; i += 512) {
        int j = i >> 7, d = i & 127;      // W1 [64][128]
        stage_b_g(W1AF, 16, j, d, W1a[i]);
        stage_b_g(W1BF, 16, j, d, W1b[i]);
        int d2 = i >> 6, j2 = i & 63;     // W2 [128][64]
        stage_b_g(W2AF, 8, d2, j2, W2a[i]);
        stage_b_g(W2BF, 8, d2, j2, W2b[i]);
    }
    if (tid < 64) { b1as[tid] = b1a[tid]; bias[192 + tid] = b1b[tid]; }
    else if (tid >= 128 && tid < 256) {
        int t = tid - 128;
        b2as[t] = b2a[t]; b2bs[t] = b2b[t]; g2s[t] = ln2g[t]; bb2s[t] = ln2b[t];
    }
    __syncthreads();

    int mt = wid >> 3;        // m-tile (0/1) for GEMV phases
    int ntw = wid & 7;        // n-tile id within phase

    for (int grp = blockIdx.x; grp < N_EDGES / 32; grp += gridDim.x) {
        int e_base = grp * 32;
        { // Phase A: mean-msg + LN2 -> x_sm + XF
            int eL = tid >> 4, l16 = tid & 15;
            int e = e_base + eL;
            float inv = 1.f / fmaxf((float)g_ecnt[e], 1.f);
            const float4* sp = reinterpret_cast<const float4*>(&g_s[(size_t)e * 128]);
            float4 v0 = sp[l16 * 2], v1 = sp[l16 * 2 + 1];
            float vals[8] = {v0.x * inv, v0.y * inv, v0.z * inv, v0.w * inv,
                             v1.x * inv, v1.y * inv, v1.z * inv, v1.w * inv};
            float s1 = 0.f, s2 = 0.f;
#pragma unroll
            for (int k = 0; k < 8; k++) { s1 += vals[k]; s2 += vals[k] * vals[k]; }
#pragma unroll
            for (int off = 8; off >= 1; off >>= 1) {
                s1 += __shfl_xor_sync(0xffffffffu, s1, off);
                s2 += __shfl_xor_sync(0xffffffffu, s2, off);
            }
            float mean = s1 * (1.f / 128.f);
            float var = fmaxf(s2 * (1.f / 128.f) - mean * mean, 0.f);
            float rstd = rsqrtf(var + EPS);
            int d0 = l16 * 8;
#pragma unroll
            for (int k = 0; k < 8; k++) {
                float xv = (vals[k] - mean) * rstd * g2s[d0 + k] + bb2s[d0 + k];
                x_sm[eL * 128 + d0 + k] = xv;
                stage_a_g(XF, 16, eL, d0 + k, xv);
            }
        }
        __syncthreads();
        { // GEMV1a: H = silu(X @ W1a^T + b1a) -> H1F
            float c[4] = {0.f, 0.f, 0.f, 0.f};
#pragma unroll
            for (int kt = 0; kt < 16; kt++) {
                uint4 au = *reinterpret_cast<uint4*>(&XF[((mt * 16 + kt) * 32 + lane) * 4]);
                uint a[4] = {au.x, au.y, au.z, au.w};
                uint2 bu = *reinterpret_cast<uint2*>(&W1AF[((ntw * 16 + kt) * 32 + lane) * 2]);
                uint b[2] = {bu.x, bu.y};
                mma_tf32(c, a, b);
            }
            int col = ntw * 8 + cq * 2;
            int row0 = mt * 16 + r, row1 = row0 + 8;
            stage_a_g(H1F, 8, row0, col,     silu_f(c[0] + b1as[col]));
            stage_a_g(H1F, 8, row0, col + 1, silu_f(c[1] + b1as[col + 1]));
            stage_a_g(H1F, 8, row1, col,     silu_f(c[2] + b1as[col]));
            stage_a_g(H1F, 8, row1, col + 1, silu_f(c[3] + b1as[col + 1]));
        }
        __syncthreads();
        { // GEMV2a: x += H @ W2a^T + b2a -> x_sm + XF
#pragma unroll
            for (int t = 0; t < 2; t++) {
                int nt2 = ntw + t * 8;
                float c[4] = {0.f, 0.f, 0.f, 0.f};
#pragma unroll
                for (int kt = 0; kt < 8; kt++) {
                    uint4 au = *reinterpret_cast<uint4*>(&H1F[((mt * 8 + kt) * 32 + lane) * 4]);
                    uint a[4] = {au.x, au.y, au.z, au.w};
                    uint2 bu = *reinterpret_cast<uint2*>(&W2AF[((nt2 * 8 + kt) * 32 + lane) * 2]);
                    uint b[2] = {bu.x, bu.y};
                    mma_tf32(c, a, b);
                }
                int col = nt2 * 8 + cq * 2;
                int row0 = mt * 16 + r, row1 = row0 + 8;
                float n00 = x_sm[row0 * 128 + col]     + c[0] + b2as[col];
                float n01 = x_sm[row0 * 128 + col + 1] + c[1] + b2as[col + 1];
                float n10 = x_sm[row1 * 128 + col]     + c[2] + b2as[col];
                float n11 = x_sm[row1 * 128 + col + 1] + c[3] + b2as[col + 1];
                x_sm[row0 * 128 + col] = n00;     x_sm[row0 * 128 + col + 1] = n01;
                x_sm[row1 * 128 + col] = n10;     x_sm[row1 * 128 + col + 1] = n11;
                stage_a_g(XF, 16, row0, col, n00); stage_a_g(XF, 16, row0, col + 1, n01);
                stage_a_g(XF, 16, row1, col, n10); stage_a_g(XF, 16, row1, col + 1, n11);
            }
        }
        __syncthreads();
        { // GEMV1b
            float c[4] = {0.f, 0.f, 0.f, 0.f};
#pragma unroll
            for (int kt = 0; kt < 16; kt++) {
                uint4 au = *reinterpret_cast<uint4*>(&XF[((mt * 16 + kt) * 32 + lane) * 4]);
                uint a[4] = {au.x, au.y, au.z, au.w};
                uint2 bu = *reinterpret_cast<uint2*>(&W1BF[((ntw * 16 + kt) * 32 + lane) * 2]);
                uint b[2] = {bu.x, bu.y};
                mma_tf32(c, a, b);
            }
            int col = ntw * 8 + cq * 2;
            int row0 = mt * 16 + r, row1 = row0 + 8;
            stage_a_g(H1F, 8, row0, col,     silu_f(c[0] + bias[192 + col]));
            stage_a_g(H1F, 8, row0, col + 1, silu_f(c[1] + bias[192 + col + 1]));
            stage_a_g(H1F, 8, row1, col,     silu_f(c[2] + bias[192 + col]));
            stage_a_g(H1F, 8, row1, col + 1, silu_f(c[3] + bias[192 + col + 1]));
        }
        __syncthreads();
        { // GEMV2b + final output
#pragma unroll
            for (int t = 0; t < 2; t++) {
                int nt2 = ntw + t * 8;
                float c[4] = {0.f, 0.f, 0.f, 0.f};
#pragma unroll
                for (int kt = 0; kt < 8; kt++) {
                    uint4 au = *reinterpret_cast<uint4*>(&H1F[((mt * 8 + kt) * 32 + lane) * 4]);
                    uint a[4] = {au.x, au.y, au.z, au.w};
                    uint2 bu = *reinterpret_cast<uint2*>(&W2BF[((nt2 * 8 + kt) * 32 + lane) * 2]);
                    uint b[2] = {bu.x, bu.y};
                    mma_tf32(c, a, b);
                }
                int col = nt2 * 8 + cq * 2;
                int row0 = mt * 16 + r, row1 = row0 + 8;
                int e0 = e_base + row0, e1 = e_base + row1;
                float f00 = x_sm[row0 * 128 + col]     + c[0] + b2bs[col];
                float f01 = x_sm[row0 * 128 + col + 1] + c[1] + b2bs[col + 1];
                float f10 = x_sm[row1 * 128 + col]     + c[2] + b2bs[col];
                float f11 = x_sm[row1 * 128 + col + 1] + c[3] + b2bs[col + 1];
                float2 nb0 = *reinterpret_cast<const float2*>(&nbr[(size_t)e0 * 128 + col]);
                float2 nb1 = *reinterpret_cast<const float2*>(&nbr[(size_t)e1 * 128 + col]);
                float2 o0 = {INV_SQRT_2 * (nb0.x + f00), INV_SQRT_2 * (nb0.y + f01)};
                float2 o1 = {INV_SQRT_2 * (nb1.x + f10), INV_SQRT_2 * (nb1.y + f11)};
                *reinterpret_cast<float2*>(&out[(size_t)e0 * 128 + col]) = o0;
                *reinterpret_cast<float2*>(&out[(size_t)e1 * 128 + col]) = o1;
            }
        }
        __syncthreads();
    }
}

// ---------- launch ----------------------------------------------------------
extern "C" void kernel_launch(void* const* d_in, const int* in_sizes, int n_in,
                              void* d_out, int out_size) {
    const float* nbr_fea   = (const float*)d_in[0];
    const float* angle_fea = (const float*)d_in[1];
    const int*   nidx      = (const int*)d_in[2];
    const int*   cai       = (const int*)d_in[4];
    const float* W_full    = (const float*)d_in[5];
    const float* W_mask    = (const float*)d_in[6];
    const float* cn_gamma  = (const float*)d_in[7];
    const float* cn_beta   = (const float*)d_in[8];
    const float* ln_core_g = (const float*)d_in[9];
    const float* ln_core_b = (const float*)d_in[10];
    const float* ln2_g     = (const float*)d_in[11];
    const float* ln2_b     = (const float*)d_in[12];
    const float* res_W1a   = (const float*)d_in[13];
    const float* res_b1a   = (const float*)d_in[14];
    const float* res_W2a   = (const float*)d_in[15];
    const float* res_b2a   = (const float*)d_in[16];
    const float* res_W1b   = (const float*)d_in[17];
    const float* res_b1b   = (const float*)d_in[18];
    const float* res_W2b   = (const float*)d_in[19];
    const float* res_b2b   = (const float*)d_in[20];
    float* out = (float*)d_out;

    static bool attr_set = false;
    if (!attr_set) {
        cudaFuncSetAttribute(k_edge, cudaFuncAttributeMaxDynamicSharedMemorySize, 176 * 1024);
        attr_set = true;
    }

    k_zero<<<1024, 256>>>();
    k_gemm_pq<<<dim3((N_EDGES + 127) / 128, 4), 256>>>(nbr_fea, W_full);
    k_gemm_angle<<<dim3(N_ANGLES / 128, 2), 256>>>(angle_fea, W_full, nidx);
    k_stats<<<N_ANGLES / 128, 256>>>(cai);
    k_finalize<<<N_CRYST, 256>>>(cn_gamma, cn_beta);
    k_msg<<<N_ANGLES / 8, 256>>>(cai, nidx, W_mask, ln_core_g, ln_core_b);
    k_edge<<<148, 512, 43648 * sizeof(float)>>>(nbr_fea, ln2_g, ln2_b,
                                                res_W1a, res_b1a, res_W2a, res_b2a,
                                                res_W1b, res_b1b, res_W2b, res_b2b, out);
}

// round 8
// speedup vs baseline: 2.3538x; 1.0041x over previous
#include <cuda_runtime.h>
#include <cuda_fp16.h>
#include <cstdint>

#define N_EDGES 100000
#define N_ANGLES 400000
#define N_CRYST 512
#define EPS 1e-5f
#define INV_SQRT_2 0.70710678118654752440f

typedef unsigned long long ull;
typedef unsigned int uint;

// ---------- scratch (static device globals; no runtime allocation) ----------
__device__ __half g_PQh[(size_t)N_EDGES * 512];   // P | Q  (fp16 storage)
__device__ __half g_hh[(size_t)N_ANGLES * 256];   // h      (fp16 storage)
__device__ float g_sum[N_CRYST * 256];
__device__ float g_sumsq[N_CRYST * 256];
__device__ int   g_cnt[N_CRYST];
__device__ float g_ca[N_CRYST * 256];
__device__ float g_cb[N_CRYST * 256];
__device__ float g_s[(size_t)N_EDGES * 128];
__device__ int   g_ecnt[N_EDGES];

__device__ __forceinline__ float silu_f(float x) { return x / (1.f + __expf(-x)); }
__device__ __forceinline__ uint tf32u(float x) {
    uint u; asm("cvt.rna.tf32.f32 %0, %1;" : "=r"(u) : "f"(x)); return u;
}
__device__ __forceinline__ void mma_tf32(float d[4], const uint a[4], const uint b[2]) {
    asm volatile(
        "mma.sync.aligned.m16n8k8.row.col.f32.tf32.tf32.f32 "
        "{%0,%1,%2,%3},{%4,%5,%6,%7},{%8,%9},{%0,%1,%2,%3};"
        : "+f"(d[0]), "+f"(d[1]), "+f"(d[2]), "+f"(d[3])
        : "r"(a[0]), "r"(a[1]), "r"(a[2]), "r"(a[3]), "r"(b[0]), "r"(b[1]));
}

// ---------- streaming (evict-first) load/store helpers ----------
__device__ __forceinline__ uint ldcs_u32(const void* p) {
    uint v; asm volatile("ld.global.cs.b32 %0, [%1];" : "=r"(v) : "l"(p)); return v;
}
__device__ __forceinline__ uint2 ldcs_u64(const void* p) {
    uint2 v; asm volatile("ld.global.cs.v2.u32 {%0,%1}, [%2];" : "=r"(v.x), "=r"(v.y) : "l"(p)); return v;
}
__device__ __forceinline__ float2 ldcs_f2(const void* p) {
    float2 v; asm volatile("ld.global.cs.v2.f32 {%0,%1}, [%2];" : "=f"(v.x), "=f"(v.y) : "l"(p)); return v;
}
__device__ __forceinline__ float4 ldcs_f4(const void* p) {
    float4 v; asm volatile("ld.global.cs.v4.f32 {%0,%1,%2,%3}, [%4];"
        : "=f"(v.x), "=f"(v.y), "=f"(v.z), "=f"(v.w) : "l"(p)); return v;
}
__device__ __forceinline__ void stcs_u32(void* p, uint v) {
    asm volatile("st.global.cs.b32 [%0], %1;" :: "l"(p), "r"(v) : "memory");
}
__device__ __forceinline__ void stcs_f2(void* p, float2 v) {
    asm volatile("st.global.cs.v2.f32 [%0], {%1,%2};" :: "l"(p), "f"(v.x), "f"(v.y) : "memory");
}
__device__ __forceinline__ uint h2u(__half2 h) { return *reinterpret_cast<uint*>(&h); }
__device__ __forceinline__ float2 u2f2(uint u) {
    __half2 h = *reinterpret_cast<__half2*>(&u); return __half22float2(h);
}

// ---------- K0: zero scratch ----------
__global__ void k_zero() {
    size_t i = (size_t)blockIdx.x * blockDim.x + threadIdx.x;
    size_t stride = (size_t)gridDim.x * blockDim.x;
    for (size_t t = i; t < (size_t)N_EDGES * 128; t += stride) g_s[t] = 0.f;
    for (size_t t = i; t < (size_t)N_EDGES; t += stride) g_ecnt[t] = 0;
    for (size_t t = i; t < (size_t)N_CRYST * 256; t += stride) { g_sum[t] = 0.f; g_sumsq[t] = 0.f; }
    for (size_t t = i; t < (size_t)N_CRYST; t += stride) g_cnt[t] = 0;
}

// ---- fragment-major staging helpers (validated layout, generalized KT) -----
__device__ __forceinline__ void stage_a_g(uint* buf, int KT, int row, int C, float v) {
    int mt = row >> 4, r = row & 15, kt = C >> 3, c = C & 7;
    int lane = (r & 7) * 4 + (c & 3);
    int slot = (r >> 3) + 2 * (c >> 2);
    buf[((mt * KT + kt) * 32 + lane) * 4 + slot] = tf32u(v);
}
__device__ __forceinline__ void stage_b_g(uint* buf, int KT, int nrow, int C, float v) {
    int nt = nrow >> 3, n = nrow & 7, kt = C >> 3, c = C & 7;
    int lane = n * 4 + (c & 3);
    int slot = c >> 2;
    buf[((nt * KT + kt) * 32 + lane) * 2 + slot] = tf32u(v);
}

// ============ tf32 MMA GEMM: BM=128, BN=128, BK=32, 256 thr (8 warps 4x2) ===
struct MmaSmem { uint a[128 * 32]; uint b[128 * 32]; };

__device__ __forceinline__ void mma_chunk(MmaSmem& sm, int wm, int wn, int lane,
                                          float acc[2][8][4]) {
#pragma unroll
    for (int kt = 0; kt < 4; kt++) {
        uint4 a0u = *reinterpret_cast<uint4*>(&sm.a[(((wm * 2 + 0) * 4 + kt) * 32 + lane) * 4]);
        uint4 a1u = *reinterpret_cast<uint4*>(&sm.a[(((wm * 2 + 1) * 4 + kt) * 32 + lane) * 4]);
        uint a0[4] = {a0u.x, a0u.y, a0u.z, a0u.w};
        uint a1[4] = {a1u.x, a1u.y, a1u.z, a1u.w};
#pragma unroll
        for (int j = 0; j < 8; j++) {
            uint2 bu = *reinterpret_cast<uint2*>(&sm.b[(((wn * 8 + j) * 4 + kt) * 32 + lane) * 2]);
            uint b[2] = {bu.x, bu.y};
            mma_tf32(acc[0][j], a0, b);
            mma_tf32(acc[1][j], a1, b);
        }
    }
}

// ---------- K1a: P/Q = nbr_fea @ W[:,64:192].T / W[:,192:320].T -------------
__global__ __launch_bounds__(256) void k_gemm_pq(const float* __restrict__ nbr,
                                                 const float* __restrict__ W) {
    __shared__ MmaSmem sm;
    int tid = threadIdx.x;
    int warp = tid >> 5, lane = tid & 31;
    int wm = warp >> 1, wn = warp & 1;
    int m_base = blockIdx.x * 128;
    int nb = blockIdx.y & 1, qsel = blockIdx.y >> 1;
    int koff = 64 + qsel * 128;
    int n_base = nb * 128;

    float acc[2][8][4];
#pragma unroll
    for (int i = 0; i < 2; i++)
#pragma unroll
        for (int j = 0; j < 8; j++)
#pragma unroll
            for (int k = 0; k < 4; k++) acc[i][j][k] = 0.f;

    for (int kc = 0; kc < 4; kc++) {
        int k0 = kc * 32;
#pragma unroll
        for (int it = 0; it < 4; it++) {
            int lin = it * 256 + tid;
            int row = lin >> 3, c4 = (lin & 7) * 4;
            int grow = m_base + row; if (grow >= N_EDGES) grow = N_EDGES - 1;
            float4 v = *reinterpret_cast<const float4*>(nbr + (size_t)grow * 128 + k0 + c4);
            stage_a_g(sm.a, 4, row, c4 + 0, v.x);
            stage_a_g(sm.a, 4, row, c4 + 1, v.y);
            stage_a_g(sm.a, 4, row, c4 + 2, v.z);
            stage_a_g(sm.a, 4, row, c4 + 3, v.w);
        }
#pragma unroll
        for (int it = 0; it < 4; it++) {
            int lin = it * 256 + tid;
            int row = lin >> 3, c4 = (lin & 7) * 4;
            float4 v = *reinterpret_cast<const float4*>(W + (size_t)(n_base + row) * 320 + koff + k0 + c4);
            stage_b_g(sm.b, 4, row, c4 + 0, v.x);
            stage_b_g(sm.b, 4, row, c4 + 1, v.y);
            stage_b_g(sm.b, 4, row, c4 + 2, v.z);
            stage_b_g(sm.b, 4, row, c4 + 3, v.w);
        }
        __syncthreads();
        mma_chunk(sm, wm, wn, lane, acc);
        __syncthreads();
    }
    int r = lane >> 2, cq = lane & 3;
#pragma unroll
    for (int mi = 0; mi < 2; mi++) {
        int R0 = m_base + wm * 32 + mi * 16 + r;
        int R1 = R0 + 8;
#pragma unroll
        for (int j = 0; j < 8; j++) {
            int gcol = qsel * 256 + n_base + wn * 64 + j * 8 + cq * 2;
            if (R0 < N_EDGES)
                *reinterpret_cast<__half2*>(&g_PQh[(size_t)R0 * 512 + gcol]) =
                    __floats2half2_rn(acc[mi][j][0], acc[mi][j][1]);
            if (R1 < N_EDGES)
                *reinterpret_cast<__half2*>(&g_PQh[(size_t)R1 * 512 + gcol]) =
                    __floats2half2_rn(acc[mi][j][2], acc[mi][j][3]);
        }
    }
}

// ---------- K1b: h = angle@Wa.T + P[i0] + Q[i1] (single-stage, K=64) --------
// dynamic smem: A frags 8192 uints | B frags 8192 uints = 64 KB
__global__ __launch_bounds__(256) void k_gemm_angle(const float* __restrict__ ang,
                                                    const float* __restrict__ W,
                                                    const int* __restrict__ nidx) {
    extern __shared__ uint dsm[];
    uint* AF = dsm;            // KT=8, 8 m-tiles
    uint* BF = dsm + 8192;     // KT=8, 16 n-tiles
    __shared__ int i0_sm[128], i1_sm[128];
    int tid = threadIdx.x;
    int warp = tid >> 5, lane = tid & 31;
    int wm = warp >> 1, wn = warp & 1;
    int m_base = blockIdx.x * 128;
    int n_base = blockIdx.y * 128;

    if (tid < 128) {
        i0_sm[tid] = nidx[(m_base + tid) * 2 + 0];
        i1_sm[tid] = nidx[(m_base + tid) * 2 + 1];
    }

    // stage A (angle rows, streamed once -> .cs) and B (weights)
#pragma unroll
    for (int it = 0; it < 8; it++) {
        int lin = it * 256 + tid;
        int row = lin >> 4, c4 = (lin & 15) * 4;
        float4 v = ldcs_f4(ang + (size_t)(m_base + row) * 64 + c4);
        stage_a_g(AF, 8, row, c4 + 0, v.x);
        stage_a_g(AF, 8, row, c4 + 1, v.y);
        stage_a_g(AF, 8, row, c4 + 2, v.z);
        stage_a_g(AF, 8, row, c4 + 3, v.w);
    }
#pragma unroll
    for (int it = 0; it < 8; it++) {
        int lin = it * 256 + tid;
        int row = lin >> 4, c4 = (lin & 15) * 4;
        float4 v = *reinterpret_cast<const float4*>(W + (size_t)(n_base + row) * 320 + c4);
        stage_b_g(BF, 8, row, c4 + 0, v.x);
        stage_b_g(BF, 8, row, c4 + 1, v.y);
        stage_b_g(BF, 8, row, c4 + 2, v.z);
        stage_b_g(BF, 8, row, c4 + 3, v.w);
    }
    __syncthreads();

    float acc[2][8][4];
#pragma unroll
    for (int i = 0; i < 2; i++)
#pragma unroll
        for (int j = 0; j < 8; j++)
#pragma unroll
            for (int k = 0; k < 4; k++) acc[i][j][k] = 0.f;

#pragma unroll
    for (int kt = 0; kt < 8; kt++) {
        uint4 a0u = *reinterpret_cast<uint4*>(&AF[(((wm * 2 + 0) * 8 + kt) * 32 + lane) * 4]);
        uint4 a1u = *reinterpret_cast<uint4*>(&AF[(((wm * 2 + 1) * 8 + kt) * 32 + lane) * 4]);
        uint a0[4] = {a0u.x, a0u.y, a0u.z, a0u.w};
        uint a1[4] = {a1u.x, a1u.y, a1u.z, a1u.w};
#pragma unroll
        for (int j = 0; j < 8; j++) {
            uint2 bu = *reinterpret_cast<uint2*>(&BF[(((wn * 8 + j) * 8 + kt) * 32 + lane) * 2]);
            uint b[2] = {bu.x, bu.y};
            mma_tf32(acc[0][j], a0, b);
            mma_tf32(acc[1][j], a1, b);
        }
    }

    // epilogue: gather P/Q (default policy -> L2-resident), add, stream h out
    int r = lane >> 2, cq = lane & 3;
#pragma unroll
    for (int mi = 0; mi < 2; mi++) {
        int lr0 = wm * 32 + mi * 16 + r;
        int lr1 = lr0 + 8;
        int R0 = m_base + lr0, R1 = m_base + lr1;
        int i0a = i0_sm[lr0], i1a = i1_sm[lr0];
        int i0b = i0_sm[lr1], i1b = i1_sm[lr1];
#pragma unroll
        for (int j = 0; j < 8; j++) {
            int gcol = n_base + wn * 64 + j * 8 + cq * 2;
            float2 p0 = __half22float2(*reinterpret_cast<const __half2*>(&g_PQh[(size_t)i0a * 512 + gcol]));
            float2 q0 = __half22float2(*reinterpret_cast<const __half2*>(&g_PQh[(size_t)i1a * 512 + 256 + gcol]));
            stcs_u32(&g_hh[(size_t)R0 * 256 + gcol],
                     h2u(__floats2half2_rn(acc[mi][j][0] + p0.x + q0.x, acc[mi][j][1] + p0.y + q0.y)));
            float2 p1 = __half22float2(*reinterpret_cast<const __half2*>(&g_PQh[(size_t)i0b * 512 + gcol]));
            float2 q1 = __half22float2(*reinterpret_cast<const __half2*>(&g_PQh[(size_t)i1b * 512 + 256 + gcol]));
            stcs_u32(&g_hh[(size_t)R1 * 256 + gcol],
                     h2u(__floats2half2_rn(acc[mi][j][2] + p1.x + q1.x, acc[mi][j][3] + p1.y + q1.y)));
        }
    }
}

// ---------- K2: crystal stats from fp16 h (sorted segments, MLP=8) ----------
__global__ __launch_bounds__(256) void k_stats(const int* __restrict__ seg) {
    __shared__ int seg_sm[128];
    int tid = threadIdx.x;
    int bi = blockIdx.x;
    if (tid < 128) seg_sm[tid] = seg[bi * 128 + tid];
    __syncthreads();
    int cp = tid & 127, halfsel = tid >> 7;
    int r0 = halfsel * 64;
    size_t rowbase = (size_t)(bi * 128 + r0);
    int cur = seg_sm[r0];
    float s0 = 0.f, s1 = 0.f, q0 = 0.f, q1 = 0.f; int c = 0;
    for (int rb = 0; rb < 64; rb += 8) {
        float2 v[8];
#pragma unroll
        for (int u = 0; u < 8; u++)
            v[u] = u2f2(ldcs_u32(&g_hh[(rowbase + rb + u) * 256 + cp * 2]));
#pragma unroll
        for (int u = 0; u < 8; u++) {
            int sg = seg_sm[r0 + rb + u];
            if (sg != cur) {
                atomicAdd(&g_sum[cur * 256 + cp * 2 + 0], s0);
                atomicAdd(&g_sum[cur * 256 + cp * 2 + 1], s1);
                atomicAdd(&g_sumsq[cur * 256 + cp * 2 + 0], q0);
                atomicAdd(&g_sumsq[cur * 256 + cp * 2 + 1], q1);
                if (cp == 0) atomicAdd(&g_cnt[cur], c);
                s0 = s1 = q0 = q1 = 0.f; c = 0; cur = sg;
            }
            s0 += v[u].x; q0 += v[u].x * v[u].x;
            s1 += v[u].y; q1 += v[u].y * v[u].y;
            c++;
        }
    }
    atomicAdd(&g_sum[cur * 256 + cp * 2 + 0], s0);
    atomicAdd(&g_sum[cur * 256 + cp * 2 + 1], s1);
    atomicAdd(&g_sumsq[cur * 256 + cp * 2 + 0], q0);
    atomicAdd(&g_sumsq[cur * 256 + cp * 2 + 1], q1);
    if (cp == 0) atomicAdd(&g_cnt[cur], c);
}

// ---------- K3: crystal-norm affine coefficients ----------------------------
__global__ void k_finalize(const float* __restrict__ gamma, const float* __restrict__ beta) {
    int c = blockIdx.x, n = threadIdx.x;
    float cnt = fmaxf((float)g_cnt[c], 1.f);
    float mean = g_sum[c * 256 + n] / cnt;
    float var = fmaxf(g_sumsq[c * 256 + n] / cnt - mean * mean, 0.f);
    float a = gamma[n] * rsqrtf(var + EPS);
    g_ca[c * 256 + n] = a;
    g_cb[c * 256 + n] = beta[n] - mean * a;
}

// ---------- K4: per-angle msg + scatter into edge sums (1 warp/angle) -------
__global__ __launch_bounds__(256) void k_msg(const int* __restrict__ seg,
                                             const int* __restrict__ nidx,
                                             const float* __restrict__ Wm,
                                             const float* __restrict__ lng,
                                             const float* __restrict__ lnb) {
    int lane = threadIdx.x & 31;
    int row = blockIdx.x * 8 + (threadIdx.x >> 5);
    const char* hbase = (const char*)&g_hh[(size_t)row * 256];
    uint2 hcu = ldcs_u64(hbase + lane * 8);
    uint2 hfu = ldcs_u64(hbase + 256 + lane * 8);
    float2 c01 = u2f2(hcu.x), c23 = u2f2(hcu.y);
    float2 f01 = u2f2(hfu.x), f23 = u2f2(hfu.y);
    float4 hc = {c01.x, c01.y, c23.x, c23.y};
    float4 hf = {f01.x, f01.y, f23.x, f23.y};
    int sg = seg[row];
    const float4* ca = reinterpret_cast<const float4*>(&g_ca[(size_t)sg * 256]);
    const float4* cb = reinterpret_cast<const float4*>(&g_cb[(size_t)sg * 256]);
    float4 ac = ca[lane], af = ca[32 + lane];
    float4 bc = cb[lane], bf = cb[32 + lane];
    float4 core, filt;
    core.x = hc.x * ac.x + bc.x; core.y = hc.y * ac.y + bc.y;
    core.z = hc.z * ac.z + bc.z; core.w = hc.w * ac.w + bc.w;
    filt.x = hf.x * af.x + bf.x; filt.y = hf.y * af.y + bf.y;
    filt.z = hf.z * af.z + bf.z; filt.w = hf.w * af.w + bf.w;
    float s1 = core.x + core.y + core.z + core.w;
    float s2 = core.x * core.x + core.y * core.y + core.z * core.z + core.w * core.w;
#pragma unroll
    for (int off = 16; off >= 1; off >>= 1) {
        s1 += __shfl_xor_sync(0xffffffffu, s1, off);
        s2 += __shfl_xor_sync(0xffffffffu, s2, off);
    }
    float mean = s1 * (1.f / 128.f);
    float var = fmaxf(s2 * (1.f / 128.f) - mean * mean, 0.f);
    float rstd = rsqrtf(var + EPS);
    float4 g4 = reinterpret_cast<const float4*>(lng)[lane];
    float4 b4 = reinterpret_cast<const float4*>(lnb)[lane];
    float4 sl;
    sl.x = silu_f((core.x - mean) * rstd * g4.x + b4.x);
    sl.y = silu_f((core.y - mean) * rstd * g4.y + b4.y);
    sl.z = silu_f((core.z - mean) * rstd * g4.z + b4.z);
    sl.w = silu_f((core.w - mean) * rstd * g4.w + b4.w);
    float4 wm = reinterpret_cast<const float4*>(Wm)[lane];
    float gp = filt.x * wm.x + filt.y * wm.y + filt.z * wm.z + filt.w * wm.w;
#pragma unroll
    for (int off = 16; off >= 1; off >>= 1) gp += __shfl_xor_sync(0xffffffffu, gp, off);
    float gate = 1.f / (1.f + __expf(-gp));
    float4 msg = {gate * sl.x, gate * sl.y, gate * sl.z, gate * sl.w};
    int src = nidx[row * 2];
    float* dst = &g_s[(size_t)src * 128 + lane * 4];
    asm volatile("red.global.add.v4.f32 [%0], {%1,%2,%3,%4};"
                 :: "l"(dst), "f"(msg.x), "f"(msg.y), "f"(msg.z), "f"(msg.w) : "memory");
    if (lane == 0) atomicAdd(&g_ecnt[src], 1);
}

// ---------- K5: per-edge LN2 + two residual MLPs, tf32 tensor cores ---------
__global__ __launch_bounds__(512) void k_edge(const float* __restrict__ nbr,
                       const float* __restrict__ ln2g, const float* __restrict__ ln2b,
                       const float* __restrict__ W1a, const float* __restrict__ b1a,
                       const float* __restrict__ W2a, const float* __restrict__ b2a,
                       const float* __restrict__ W1b, const float* __restrict__ b1b,
                       const float* __restrict__ W2b, const float* __restrict__ b2b,
                       float* __restrict__ out) {
    extern __shared__ uint usm[];
    uint* W1AF = usm;
    uint* W2AF = usm + 8192;
    uint* W1BF = usm + 16384;
    uint* W2BF = usm + 24576;
    uint* XF   = usm + 32768;
    uint* H1F  = usm + 36864;
    float* x_sm = (float*)(usm + 38912);
    float* bias = (float*)(usm + 43008);
    float* b1as = bias;
    float* b2as = bias + 64;
    float* b1bs = bias + 192;
    float* b2bs = bias + 256;
    float* g2s  = bias + 384;
    float* bb2s = bias + 512;

    int tid = threadIdx.x;
    int wid = tid >> 5, lane = tid & 31;
    int r = lane >> 2, cq = lane & 3;

    for (int i = tid; i < 8192; i += 512) {
        int j = i >> 7, d = i & 127;
        stage_b_g(W1AF, 16, j, d, W1a[i]);
        stage_b_g(W1BF, 16, j, d, W1b[i]);
        int d2 = i >> 6, j2 = i & 63;
        stage_b_g(W2AF, 8, d2, j2, W2a[i]);
        stage_b_g(W2BF, 8, d2, j2, W2b[i]);
    }
    if (tid < 64) { b1as[tid] = b1a[tid]; bias[192 + tid] = b1b[tid]; }
    else if (tid >= 128 && tid < 256) {
        int t = tid - 128;
        b2as[t] = b2a[t]; b2bs[t] = b2b[t]; g2s[t] = ln2g[t]; bb2s[t] = ln2b[t];
    }
    __syncthreads();

    int mt = wid >> 3;
    int ntw = wid & 7;

    for (int grp = blockIdx.x; grp < N_EDGES / 32; grp += gridDim.x) {
        int e_base = grp * 32;
        {
            int eL = tid >> 4, l16 = tid & 15;
            int e = e_base + eL;
            float inv = 1.f / fmaxf((float)g_ecnt[e], 1.f);
            float4 v0 = ldcs_f4(&g_s[(size_t)e * 128 + l16 * 8]);
            float4 v1 = ldcs_f4(&g_s[(size_t)e * 128 + l16 * 8 + 4]);
            float vals[8] = {v0.x * inv, v0.y * inv, v0.z * inv, v0.w * inv,
                             v1.x * inv, v1.y * inv, v1.z * inv, v1.w * inv};
            float s1 = 0.f, s2 = 0.f;
#pragma unroll
            for (int k = 0; k < 8; k++) { s1 += vals[k]; s2 += vals[k] * vals[k]; }
#pragma unroll
            for (int off = 8; off >= 1; off >>= 1) {
                s1 += __shfl_xor_sync(0xffffffffu, s1, off);
                s2 += __shfl_xor_sync(0xffffffffu, s2, off);
            }
            float mean = s1 * (1.f / 128.f);
            float var = fmaxf(s2 * (1.f / 128.f) - mean * mean, 0.f);
            float rstd = rsqrtf(var + EPS);
            int d0 = l16 * 8;
#pragma unroll
            for (int k = 0; k < 8; k++) {
                float xv = (vals[k] - mean) * rstd * g2s[d0 + k] + bb2s[d0 + k];
                x_sm[eL * 128 + d0 + k] = xv;
                stage_a_g(XF, 16, eL, d0 + k, xv);
            }
        }
        __syncthreads();
        {
            float c[4] = {0.f, 0.f, 0.f, 0.f};
#pragma unroll
            for (int kt = 0; kt < 16; kt++) {
                uint4 au = *reinterpret_cast<uint4*>(&XF[((mt * 16 + kt) * 32 + lane) * 4]);
                uint a[4] = {au.x, au.y, au.z, au.w};
                uint2 bu = *reinterpret_cast<uint2*>(&W1AF[((ntw * 16 + kt) * 32 + lane) * 2]);
                uint b[2] = {bu.x, bu.y};
                mma_tf32(c, a, b);
            }
            int col = ntw * 8 + cq * 2;
            int row0 = mt * 16 + r, row1 = row0 + 8;
            stage_a_g(H1F, 8, row0, col,     silu_f(c[0] + b1as[col]));
            stage_a_g(H1F, 8, row0, col + 1, silu_f(c[1] + b1as[col + 1]));
            stage_a_g(H1F, 8, row1, col,     silu_f(c[2] + b1as[col]));
            stage_a_g(H1F, 8, row1, col + 1, silu_f(c[3] + b1as[col + 1]));
        }
        __syncthreads();
        {
#pragma unroll
            for (int t = 0; t < 2; t++) {
                int nt2 = ntw + t * 8;
                float c[4] = {0.f, 0.f, 0.f, 0.f};
#pragma unroll
                for (int kt = 0; kt < 8; kt++) {
                    uint4 au = *reinterpret_cast<uint4*>(&H1F[((mt * 8 + kt) * 32 + lane) * 4]);
                    uint a[4] = {au.x, au.y, au.z, au.w};
                    uint2 bu = *reinterpret_cast<uint2*>(&W2AF[((nt2 * 8 + kt) * 32 + lane) * 2]);
                    uint b[2] = {bu.x, bu.y};
                    mma_tf32(c, a, b);
                }
                int col = nt2 * 8 + cq * 2;
                int row0 = mt * 16 + r, row1 = row0 + 8;
                float n00 = x_sm[row0 * 128 + col]     + c[0] + b2as[col];
                float n01 = x_sm[row0 * 128 + col + 1] + c[1] + b2as[col + 1];
                float n10 = x_sm[row1 * 128 + col]     + c[2] + b2as[col];
                float n11 = x_sm[row1 * 128 + col + 1] + c[3] + b2as[col + 1];
                x_sm[row0 * 128 + col] = n00;     x_sm[row0 * 128 + col + 1] = n01;
                x_sm[row1 * 128 + col] = n10;     x_sm[row1 * 128 + col + 1] = n11;
                stage_a_g(XF, 16, row0, col, n00); stage_a_g(XF, 16, row0, col + 1, n01);
                stage_a_g(XF, 16, row1, col, n10); stage_a_g(XF, 16, row1, col + 1, n11);
            }
        }
        __syncthreads();
        {
            float c[4] = {0.f, 0.f, 0.f, 0.f};
#pragma unroll
            for (int kt = 0; kt < 16; kt++) {
                uint4 au = *reinterpret_cast<uint4*>(&XF[((mt * 16 + kt) * 32 + lane) * 4]);
                uint a[4] = {au.x, au.y, au.z, au.w};
                uint2 bu = *reinterpret_cast<uint2*>(&W1BF[((ntw * 16 + kt) * 32 + lane) * 2]);
                uint b[2] = {bu.x, bu.y};
                mma_tf32(c, a, b);
            }
            int col = ntw * 8 + cq * 2;
            int row0 = mt * 16 + r, row1 = row0 + 8;
            stage_a_g(H1F, 8, row0, col,     silu_f(c[0] + bias[192 + col]));
            stage_a_g(H1F, 8, row0, col + 1, silu_f(c[1] + bias[192 + col + 1]));
            stage_a_g(H1F, 8, row1, col,     silu_f(c[2] + bias[192 + col]));
            stage_a_g(H1F, 8, row1, col + 1, silu_f(c[3] + bias[192 + col + 1]));
        }
        __syncthreads();
        {
#pragma unroll
            for (int t = 0; t < 2; t++) {
                int nt2 = ntw + t * 8;
                float c[4] = {0.f, 0.f, 0.f, 0.f};
#pragma unroll
                for (int kt = 0; kt < 8; kt++) {
                    uint4 au = *reinterpret_cast<uint4*>(&H1F[((mt * 8 + kt) * 32 + lane) * 4]);
                    uint a[4] = {au.x, au.y, au.z, au.w};
                    uint2 bu = *reinterpret_cast<uint2*>(&W2BF[((nt2 * 8 + kt) * 32 + lane) * 2]);
                    uint b[2] = {bu.x, bu.y};
                    mma_tf32(c, a, b);
                }
                int col = nt2 * 8 + cq * 2;
                int row0 = mt * 16 + r, row1 = row0 + 8;
                int e0 = e_base + row0, e1 = e_base + row1;
                float f00 = x_sm[row0 * 128 + col]     + c[0] + b2bs[col];
                float f01 = x_sm[row0 * 128 + col + 1] + c[1] + b2bs[col + 1];
                float f10 = x_sm[row1 * 128 + col]     + c[2] + b2bs[col];
                float f11 = x_sm[row1 * 128 + col + 1] + c[3] + b2bs[col + 1];
                float2 nb0 = ldcs_f2(&nbr[(size_t)e0 * 128 + col]);
                float2 nb1 = ldcs_f2(&nbr[(size_t)e1 * 128 + col]);
                float2 o0 = {INV_SQRT_2 * (nb0.x + f00), INV_SQRT_2 * (nb0.y + f01)};
                float2 o1 = {INV_SQRT_2 * (nb1.x + f10), INV_SQRT_2 * (nb1.y + f11)};
                stcs_f2(&out[(size_t)e0 * 128 + col], o0);
                stcs_f2(&out[(size_t)e1 * 128 + col], o1);
            }
        }
        __syncthreads();
    }
}

// ---------- launch ----------------------------------------------------------
extern "C" void kernel_launch(void* const* d_in, const int* in_sizes, int n_in,
                              void* d_out, int out_size) {
    const float* nbr_fea   = (const float*)d_in[0];
    const float* angle_fea = (const float*)d_in[1];
    const int*   nidx      = (const int*)d_in[2];
    const int*   cai       = (const int*)d_in[4];
    const float* W_full    = (const float*)d_in[5];
    const float* W_mask    = (const float*)d_in[6];
    const float* cn_gamma  = (const float*)d_in[7];
    const float* cn_beta   = (const float*)d_in[8];
    const float* ln_core_g = (const float*)d_in[9];
    const float* ln_core_b = (const float*)d_in[10];
    const float* ln2_g     = (const float*)d_in[11];
    const float* ln2_b     = (const float*)d_in[12];
    const float* res_W1a   = (const float*)d_in[13];
    const float* res_b1a   = (const float*)d_in[14];
    const float* res_W2a   = (const float*)d_in[15];
    const float* res_b2a   = (const float*)d_in[16];
    const float* res_W1b   = (const float*)d_in[17];
    const float* res_b1b   = (const float*)d_in[18];
    const float* res_W2b   = (const float*)d_in[19];
    const float* res_b2b   = (const float*)d_in[20];
    float* out = (float*)d_out;

    static bool attr_set = false;
    if (!attr_set) {
        cudaFuncSetAttribute(k_edge, cudaFuncAttributeMaxDynamicSharedMemorySize, 176 * 1024);
        cudaFuncSetAttribute(k_gemm_angle, cudaFuncAttributeMaxDynamicSharedMemorySize, 68 * 1024);
        attr_set = true;
    }

    k_zero<<<1024, 256>>>();
    k_gemm_pq<<<dim3((N_EDGES + 127) / 128, 4), 256>>>(nbr_fea, W_full);
    k_gemm_angle<<<dim3(N_ANGLES / 128, 2), 256, 65536>>>(angle_fea, W_full, nidx);
    k_stats<<<N_ANGLES / 128, 256>>>(cai);
    k_finalize<<<N_CRYST, 256>>>(cn_gamma, cn_beta);
    k_msg<<<N_ANGLES / 8, 256>>>(cai, nidx, W_mask, ln_core_g, ln_core_b);
    k_edge<<<148, 512, 43648 * sizeof(float)>>>(nbr_fea, ln2_g, ln2_b,
                                                res_W1a, res_b1a, res_W2a, res_b2a,
                                                res_W1b, res_b1b, res_W2b, res_b2b, out);
}